// round 4
// baseline (speedup 1.0000x reference)
#include <cuda_runtime.h>

// ---------------------------------------------------------------------------
// HiLo attention, fp32.
// x: (4, 512, 64, 64)  -> per-batch this is exactly A^T (K=512 rows, M=4096
// cols, row-major) for a TN GEMM. All 5 GEMMs use one kernel.
// ---------------------------------------------------------------------------

#define NBATCH 4

// scratch layout (floats)
#define OFF_POOL  0L                  // pooledT (B,512,1024)      2,097,152
#define OFF_HQKV  2097152L            // hqkv    (B,4096,768)     12,582,912
#define OFF_LQ    14680064L           // lq      (B,4096,256)      4,194,304
#define OFF_LKV   18874368L           // lkv     (B,1024,512)      2,097,152
#define OFF_HOUT  20971520L           // houtT   (B,256,4096)      4,194,304
#define OFF_LOT   25165824L           // loT     (B,256,4096)      4,194,304
#define SCRATCH_FLOATS 29360128L

__device__ float g_scratch[SCRATCH_FLOATS];

// ---------------------------------------------------------------------------
// 2x2 mean pool:  pooledT[b][c][g] = mean of x[b][c] over window g
// ---------------------------------------------------------------------------
__global__ __launch_bounds__(256)
void pool_kernel(const float* __restrict__ x, float* __restrict__ pooledT) {
    long idx = (long)blockIdx.x * 256 + threadIdx.x;   // B*512*1024 = 2^21 total
    int g = (int)(idx & 1023);
    int c = (int)((idx >> 10) & 511);
    int b = (int)(idx >> 19);
    int gh = g >> 5, gw = g & 31;
    const float* p = x + ((long)(b * 512 + c) << 12) + (gh << 7) + (gw << 1);
    pooledT[idx] = 0.25f * (p[0] + p[1] + p[64] + p[65]);
}

// ---------------------------------------------------------------------------
// Generic batched TN SGEMM: C[b] = A[b]^T * Bw   (A stored K-major: K x lda)
// 128x128 tile, K-step 8, 256 threads, 8x8 microtile, register prefetch.
// TRANSC: write C column-major into d_out at channel offset coff (+ bias).
// Requires M%128==0, N%128==0, K%8==0 (all shapes here satisfy this).
// ---------------------------------------------------------------------------
template<int TRANSC, int BIAS>
__global__ __launch_bounds__(256)
void sgemm_tn(const float* __restrict__ A, long aBatch, int lda,
              const float* __restrict__ Bw, int ldb,
              float* __restrict__ C, long cBatch, int ldc, int coff,
              const float* __restrict__ bias, int K) {
    __shared__ float As[8][128];
    __shared__ float Bs[8][128];
    int tid = threadIdx.x;
    int bm = blockIdx.x, bn = blockIdx.y, b = blockIdx.z;
    const float* Ab = A + (long)b * aBatch + bm * 128;
    const float* Bb = Bw + bn * 128;
    int la_k = tid >> 5;             // 0..7
    int la_m = (tid & 31) << 2;      // 0..124
    int tx = tid & 15, ty = tid >> 4;

    float acc[8][8];
#pragma unroll
    for (int i = 0; i < 8; i++)
#pragma unroll
        for (int j = 0; j < 8; j++) acc[i][j] = 0.f;

    int KT = K >> 3;
    float4 ra = *(const float4*)(Ab + la_k * lda + la_m);
    float4 rb = *(const float4*)(Bb + la_k * ldb + la_m);

    for (int kt = 0; kt < KT; ++kt) {
        *(float4*)&As[la_k][la_m] = ra;
        *(float4*)&Bs[la_k][la_m] = rb;
        __syncthreads();
        if (kt + 1 < KT) {
            int k8 = (kt + 1) * 8 + la_k;
            ra = *(const float4*)(Ab + (long)k8 * lda + la_m);
            rb = *(const float4*)(Bb + (long)k8 * ldb + la_m);
        }
#pragma unroll
        for (int kk = 0; kk < 8; ++kk) {
            float a[8], bv[8];
            *(float4*)(a)     = *(float4*)&As[kk][ty << 2];
            *(float4*)(a + 4) = *(float4*)&As[kk][64 + (ty << 2)];
            *(float4*)(bv)     = *(float4*)&Bs[kk][tx << 2];
            *(float4*)(bv + 4) = *(float4*)&Bs[kk][64 + (tx << 2)];
#pragma unroll
            for (int i = 0; i < 8; i++)
#pragma unroll
                for (int j = 0; j < 8; j++)
                    acc[i][j] += a[i] * bv[j];
        }
        __syncthreads();
    }

    if (TRANSC) {
        float bs[8];
#pragma unroll
        for (int j = 0; j < 8; j++) {
            int n = bn * 128 + ((j < 4) ? (tx * 4 + j) : (64 + tx * 4 + j - 4));
            bs[j] = BIAS ? bias[n] : 0.f;
        }
#pragma unroll
        for (int i = 0; i < 8; i++) {
            int m = bm * 128 + ((i < 4) ? (ty * 4 + i) : (64 + ty * 4 + i - 4));
#pragma unroll
            for (int j = 0; j < 8; j++) {
                int n = bn * 128 + ((j < 4) ? (tx * 4 + j) : (64 + tx * 4 + j - 4));
                C[(long)b * cBatch + (long)(coff + n) * ldc + m] = acc[i][j] + bs[j];
            }
        }
    } else {
#pragma unroll
        for (int i = 0; i < 8; i++) {
            int m = bm * 128 + ((i < 4) ? (ty * 4 + i) : (64 + ty * 4 + i - 4));
            long cb = (long)b * cBatch + (long)m * ldc + bn * 128;
            float4 v0 = make_float4(acc[i][0], acc[i][1], acc[i][2], acc[i][3]);
            float4 v1 = make_float4(acc[i][4], acc[i][5], acc[i][6], acc[i][7]);
            *(float4*)&C[cb + (tx << 2)] = v0;
            *(float4*)&C[cb + 64 + (tx << 2)] = v1;
        }
    }
}

// ---------------------------------------------------------------------------
// Hi-fi windowed attention: one CTA (128 thr) per (b, window g).
// warp = head; 4 tokens x 4 heads x 64 dims. Output written channel-major
// (houtT: B x 256 x 4096) so h_proj can reuse the TN GEMM.
// ---------------------------------------------------------------------------
__global__ __launch_bounds__(128)
void hifi_attn(const float* __restrict__ hqkv, float* __restrict__ houtT) {
    __shared__ float sq[4][772];   // 4 tokens x 768 (+4 pad vs bank conflicts)
    int g = blockIdx.x, b = blockIdx.y;
    int gh = g >> 5, gw = g & 31;
    int tid = threadIdx.x;
    int t00 = (gh << 7) + (gw << 1);          // token (2gh, 2gw)
    const float* base = hqkv + (long)b * 4096 * 768;
#pragma unroll
    for (int it = 0; it < 6; ++it) {
        int idx = tid + it * 128;             // 0..767 float4 units
        int n = idx / 192, c4 = idx % 192;
        int t = t00 + ((n >> 1) << 6) + (n & 1);
        *(float4*)&sq[n][c4 * 4] = *(const float4*)(base + (long)t * 768 + c4 * 4);
    }
    __syncthreads();

    int head = tid >> 5, lane = tid & 31;
    int n = (lane >> 2) & 3, m = lane & 3;
    const float* qn = &sq[n][head * 64];
    const float* km = &sq[m][256 + head * 64];
    float s = 0.f;
#pragma unroll
    for (int k = 0; k < 64; ++k) s += qn[k] * km[k];
    s *= 0.125f;

    float mx = fmaxf(s, __shfl_xor_sync(0xffffffffu, s, 1));
    mx = fmaxf(mx, __shfl_xor_sync(0xffffffffu, mx, 2));
    float p = __expf(s - mx);
    float sum = p;
    sum += __shfl_xor_sync(0xffffffffu, sum, 1);
    sum += __shfl_xor_sync(0xffffffffu, sum, 2);
    p = p / sum;

    int no = lane >> 3;
    int d0 = (lane & 7) << 3;
    float o[8];
#pragma unroll
    for (int dd = 0; dd < 8; ++dd) o[dd] = 0.f;
#pragma unroll
    for (int mm = 0; mm < 4; ++mm) {
        float pm = __shfl_sync(0xffffffffu, p, no * 4 + mm);
        const float* vm = &sq[mm][512 + head * 64 + d0];
#pragma unroll
        for (int dd = 0; dd < 8; ++dd) o[dd] += pm * vm[dd];
    }
    int t = t00 + ((no >> 1) << 6) + (no & 1);
    float* ob = houtT + ((long)(b * 256 + head * 64 + d0)) * 4096 + t;
#pragma unroll
    for (int dd = 0; dd < 8; ++dd) ob[(long)dd * 4096] = o[dd];
}

// ---------------------------------------------------------------------------
// Lo-fi flash attention: CTA = 64 queries x one (b,head); 16 chunks of 64 keys.
// smem: Qs[r][d] (natural), KP (K d-major with xor swizzle, reused for P
// j-major with xor swizzle), Vs[j][d] (natural). 48 KB total.
// Softmax state (m,l) replicated across the 16 tx threads of a row group.
// Output written channel-major (loT: B x 256 x 4096) for the l_proj GEMM.
// ---------------------------------------------------------------------------
__global__ __launch_bounds__(256)
void lofi_flash(const float* __restrict__ lq, const float* __restrict__ lkv,
                float* __restrict__ loT) {
    __shared__ float Qs[4096];
    __shared__ float KP[4096];
    __shared__ float Vs[4096];
    int tid = threadIdx.x;
    int tx = tid & 15, ty = tid >> 4;
    int qb = blockIdx.x, head = blockIdx.y, b = blockIdx.z;
    int t0 = qb << 6;

    const float* lqb = lq + ((long)(b * 4096 + t0)) * 256 + head * 64;
#pragma unroll
    for (int it = 0; it < 4; ++it) {
        int idx = tid + it * 256;
        int t = idx >> 4, d4 = idx & 15;
        float4 v = *(const float4*)(lqb + t * 256 + d4 * 4);
        v.x *= 0.125f; v.y *= 0.125f; v.z *= 0.125f; v.w *= 0.125f;
        *(float4*)&Qs[t * 64 + d4 * 4] = v;
    }

    float acc[4][4], m_i[4], l_i[4];
#pragma unroll
    for (int i = 0; i < 4; i++) {
        m_i[i] = -1e30f; l_i[i] = 0.f;
#pragma unroll
        for (int j = 0; j < 4; j++) acc[i][j] = 0.f;
    }

    const float* kvb = lkv + (long)b * 1024 * 512 + head * 64;

    for (int ch = 0; ch < 16; ++ch) {
        __syncthreads();   // prior-chunk KP/Vs reads done (covers Q load on ch=0)
#pragma unroll
        for (int it = 0; it < 4; ++it) {
            int idx = tid + it * 256;
            int j = idx >> 4, d4 = idx & 15;
            const float* row = kvb + (long)((ch << 6) + j) * 512;
            float4 kv4 = *(const float4*)(row + d4 * 4);
            int sl = (((j >> 2) ^ d4) & 15) << 2;
            int jo = j & 3;
            KP[(d4 * 4 + 0) * 64 + sl + jo] = kv4.x;
            KP[(d4 * 4 + 1) * 64 + sl + jo] = kv4.y;
            KP[(d4 * 4 + 2) * 64 + sl + jo] = kv4.z;
            KP[(d4 * 4 + 3) * 64 + sl + jo] = kv4.w;
            *(float4*)&Vs[j * 64 + d4 * 4] = *(const float4*)(row + 256 + d4 * 4);
        }
        __syncthreads();

        // S = Q * K^T (scale folded into Q)
        float s[4][4];
#pragma unroll
        for (int i = 0; i < 4; i++)
#pragma unroll
            for (int j = 0; j < 4; j++) s[i][j] = 0.f;
#pragma unroll 4
        for (int k = 0; k < 64; ++k) {
            float4 bv = *(float4*)&KP[k * 64 + (((tx ^ (k >> 2)) & 15) << 2)];
#pragma unroll
            for (int i = 0; i < 4; i++) {
                float a = Qs[(ty * 4 + i) * 64 + k];
                s[i][0] += a * bv.x; s[i][1] += a * bv.y;
                s[i][2] += a * bv.z; s[i][3] += a * bv.w;
            }
        }

        // online softmax (reduction across the 16 tx lanes of each row group)
#pragma unroll
        for (int i = 0; i < 4; i++) {
            float mx = fmaxf(fmaxf(s[i][0], s[i][1]), fmaxf(s[i][2], s[i][3]));
            mx = fmaxf(mx, __shfl_xor_sync(0xffffffffu, mx, 1));
            mx = fmaxf(mx, __shfl_xor_sync(0xffffffffu, mx, 2));
            mx = fmaxf(mx, __shfl_xor_sync(0xffffffffu, mx, 4));
            mx = fmaxf(mx, __shfl_xor_sync(0xffffffffu, mx, 8));
            float mnew = fmaxf(m_i[i], mx);
            float alpha = __expf(m_i[i] - mnew);
            float sum = 0.f;
#pragma unroll
            for (int j = 0; j < 4; j++) {
                s[i][j] = __expf(s[i][j] - mnew);
                sum += s[i][j];
            }
            sum += __shfl_xor_sync(0xffffffffu, sum, 1);
            sum += __shfl_xor_sync(0xffffffffu, sum, 2);
            sum += __shfl_xor_sync(0xffffffffu, sum, 4);
            sum += __shfl_xor_sync(0xffffffffu, sum, 8);
            l_i[i] = l_i[i] * alpha + sum;
            m_i[i] = mnew;
#pragma unroll
            for (int j = 0; j < 4; j++) acc[i][j] *= alpha;
        }

        __syncthreads();   // all KP (K) reads done before P overwrites it
        int sl = ((ty ^ tx) & 15) << 2;
#pragma unroll
        for (int jj = 0; jj < 4; jj++)
#pragma unroll
            for (int i = 0; i < 4; i++)
                KP[(tx * 4 + jj) * 64 + sl + i] = s[i][jj];
        __syncthreads();

        // O += P * V
#pragma unroll 4
        for (int j = 0; j < 64; ++j) {
            float4 bv = *(float4*)&Vs[j * 64 + (tx << 2)];
            int so = j * 64 + (((ty ^ (j >> 2)) & 15) << 2);
#pragma unroll
            for (int i = 0; i < 4; i++) {
                float a = KP[so + i];
                acc[i][0] += a * bv.x; acc[i][1] += a * bv.y;
                acc[i][2] += a * bv.z; acc[i][3] += a * bv.w;
            }
        }
    }

    float* outb = loT + ((long)(b * 256 + head * 64 + tx * 4)) * 4096 + t0;
#pragma unroll
    for (int i = 0; i < 4; i++) {
        float inv = __frcp_rn(l_i[i]);
#pragma unroll
        for (int dd = 0; dd < 4; dd++)
            outb[(long)dd * 4096 + ty * 4 + i] = acc[i][dd] * inv;
    }
}

// ---------------------------------------------------------------------------
extern "C" void kernel_launch(void* const* d_in, const int* in_sizes, int n_in,
                              void* d_out, int out_size) {
    const float* x        = (const float*)d_in[0];
    const float* h_qkv_w  = (const float*)d_in[1];
    const float* h_proj_w = (const float*)d_in[2];
    const float* h_proj_b = (const float*)d_in[3];
    const float* l_q_w    = (const float*)d_in[4];
    const float* l_kv_w   = (const float*)d_in[5];
    const float* l_proj_w = (const float*)d_in[6];
    const float* l_proj_b = (const float*)d_in[7];
    float* out = (float*)d_out;

    float* scratch = nullptr;
    cudaGetSymbolAddress((void**)&scratch, g_scratch);
    float* pooledT = scratch + OFF_POOL;
    float* hqkv    = scratch + OFF_HQKV;
    float* lqv     = scratch + OFF_LQ;
    float* lkv     = scratch + OFF_LKV;
    float* houtT   = scratch + OFF_HOUT;
    float* loT     = scratch + OFF_LOT;

    // pooled (B,512,1024) channel-major = A^T for l_kv GEMM
    pool_kernel<<<8192, 256>>>(x, pooledT);

    // hqkv (B,4096,768) = x^T @ h_qkv_w
    sgemm_tn<0, 0><<<dim3(32, 6, NBATCH), 256>>>(
        x, 2097152L, 4096, h_qkv_w, 768, hqkv, 4096L * 768, 768, 0, nullptr, 512);
    // lq (B,4096,256) = x^T @ l_q_w
    sgemm_tn<0, 0><<<dim3(32, 2, NBATCH), 256>>>(
        x, 2097152L, 4096, l_q_w, 256, lqv, 4096L * 256, 256, 0, nullptr, 512);
    // lkv (B,1024,512) = pooled^T @ l_kv_w
    sgemm_tn<0, 0><<<dim3(8, 4, NBATCH), 256>>>(
        pooledT, 524288L, 1024, l_kv_w, 512, lkv, 1024L * 512, 512, 0, nullptr, 512);

    hifi_attn<<<dim3(1024, NBATCH), 128>>>(hqkv, houtT);
    lofi_flash<<<dim3(64, 4, NBATCH), 256>>>(lqv, lkv, loT);

    // out[:, 0:256]  = (houtT^T @ h_proj_w + b), written NCHW channel-major
    sgemm_tn<1, 1><<<dim3(32, 2, NBATCH), 256>>>(
        houtT, 1048576L, 4096, h_proj_w, 256, out, 2097152L, 4096, 0, h_proj_b, 256);
    // out[:, 256:512] = (loT^T @ l_proj_w + b)
    sgemm_tn<1, 1><<<dim3(32, 2, NBATCH), 256>>>(
        loT, 1048576L, 4096, l_proj_w, 256, out, 2097152L, 4096, 256, l_proj_b, 256);
}

// round 5
// speedup vs baseline: 2.3615x; 2.3615x over previous
#include <cuda_runtime.h>

// ---------------------------------------------------------------------------
// HiLo attention. GEMMs + lo-fi flash attention on TF32 tensor cores
// (mma.sync.m16n8k8), fp32 accumulate. rel-err budget ~2e-4 vs 1e-3 threshold.
// x: (4, 512, 64, 64) -> per-batch exactly A^T (K-major) for TN GEMMs.
// ---------------------------------------------------------------------------

#define NBATCH 4

// scratch layout (floats)
#define OFF_POOL  0L                  // pooledT (B,512,1024)
#define OFF_HQKV  2097152L            // hqkv    (B,4096,768)
#define OFF_LQ    14680064L           // lq      (B,4096,256)
#define OFF_LKV   18874368L           // lkv     (B,1024,512)
#define OFF_HOUT  20971520L           // houtT   (B,256,4096)
#define OFF_LOT   25165824L           // loT     (B,256,4096)
#define SCRATCH_FLOATS 29360128L

__device__ float g_scratch[SCRATCH_FLOATS];

// ---------------------------------------------------------------------------
__device__ __forceinline__ unsigned f2tf(float f) {
    unsigned r;
    asm("cvt.rna.tf32.f32 %0, %1;" : "=r"(r) : "f"(f));
    return r;
}

__device__ __forceinline__ void mma8(float* d, const unsigned* a,
                                     unsigned b0, unsigned b1) {
    asm volatile(
        "mma.sync.aligned.m16n8k8.row.col.f32.tf32.tf32.f32 "
        "{%0,%1,%2,%3}, {%4,%5,%6,%7}, {%8,%9}, {%0,%1,%2,%3};\n"
        : "+f"(d[0]), "+f"(d[1]), "+f"(d[2]), "+f"(d[3])
        : "r"(a[0]), "r"(a[1]), "r"(a[2]), "r"(a[3]), "r"(b0), "r"(b1));
}

__device__ __forceinline__ uint4 tf4(float4 v) {
    uint4 u;
    u.x = f2tf(v.x); u.y = f2tf(v.y); u.z = f2tf(v.z); u.w = f2tf(v.w);
    return u;
}

// ---------------------------------------------------------------------------
// 2x2 mean pool:  pooledT[b][c][g] = mean of x[b][c] over window g
// ---------------------------------------------------------------------------
__global__ __launch_bounds__(256)
void pool_kernel(const float* __restrict__ x, float* __restrict__ pooledT) {
    long idx = (long)blockIdx.x * 256 + threadIdx.x;
    int g = (int)(idx & 1023);
    int c = (int)((idx >> 10) & 511);
    int b = (int)(idx >> 19);
    int gh = g >> 5, gw = g & 31;
    const float* p = x + ((long)(b * 512 + c) << 12) + (gh << 7) + (gw << 1);
    pooledT[idx] = 0.25f * (p[0] + p[1] + p[64] + p[65]);
}

// ---------------------------------------------------------------------------
// TF32 batched TN GEMM: C[b] = A[b]^T * Bw   (A stored K-major: K x lda)
// 128x128 tile, BK=32, 256 threads, warp grid 2x4, warp tile 64x32,
// mma.sync.m16n8k8.tf32. Smem stride 136 words (== 8 mod 32): conflict-free
// fragment loads. TRANSC: write C column-major at channel offset coff + bias.
// Requires M%128==0, N%128==0, K%32==0.
// ---------------------------------------------------------------------------
#define SGS 136   // smem row stride in words

template<int TRANSC, int BIAS>
__global__ __launch_bounds__(256)
void tgemm_tn(const float* __restrict__ A, long aBatch, int lda,
              const float* __restrict__ Bw, int ldb,
              float* __restrict__ C, long cBatch, int ldc, int coff,
              const float* __restrict__ bias, int K) {
    __shared__ unsigned As[32 * SGS];
    __shared__ unsigned Bs[32 * SGS];
    int tid = threadIdx.x;
    int bm = blockIdx.x, bn = blockIdx.y, b = blockIdx.z;
    const float* Ab = A + (long)b * aBatch + bm * 128;
    const float* Bb = Bw + bn * 128;
    int lk = tid >> 5;               // 0..7
    int lm4 = (tid & 31) << 2;       // 0..124
    int warp = tid >> 5, lane = tid & 31;
    int wm = warp >> 2, wn = warp & 3;
    int g = lane >> 2, t = lane & 3;

    float acc[4][4][4];
#pragma unroll
    for (int i = 0; i < 4; i++)
#pragma unroll
        for (int j = 0; j < 4; j++)
#pragma unroll
            for (int r = 0; r < 4; r++) acc[i][j][r] = 0.f;

    int KT = K >> 5;
    float4 ra[4], rb[4];
#pragma unroll
    for (int it = 0; it < 4; ++it) {
        int k = lk + 8 * it;
        ra[it] = *(const float4*)(Ab + (long)k * lda + lm4);
        rb[it] = *(const float4*)(Bb + (long)k * ldb + lm4);
    }

    for (int kt = 0; kt < KT; ++kt) {
#pragma unroll
        for (int it = 0; it < 4; ++it) {
            int k = lk + 8 * it;
            *(uint4*)&As[k * SGS + lm4] = tf4(ra[it]);
            *(uint4*)&Bs[k * SGS + lm4] = tf4(rb[it]);
        }
        __syncthreads();
        if (kt + 1 < KT) {
#pragma unroll
            for (int it = 0; it < 4; ++it) {
                int k = (kt + 1) * 32 + lk + 8 * it;
                ra[it] = *(const float4*)(Ab + (long)k * lda + lm4);
                rb[it] = *(const float4*)(Bb + (long)k * ldb + lm4);
            }
        }
#pragma unroll
        for (int kk = 0; kk < 4; ++kk) {
            int kO = kk * 8;
            unsigned af[4][4], bf[4][2];
#pragma unroll
            for (int mi = 0; mi < 4; ++mi) {
                int m = wm * 64 + mi * 16 + g;
                af[mi][0] = As[(kO + t) * SGS + m];
                af[mi][1] = As[(kO + t) * SGS + m + 8];
                af[mi][2] = As[(kO + t + 4) * SGS + m];
                af[mi][3] = As[(kO + t + 4) * SGS + m + 8];
            }
#pragma unroll
            for (int ni = 0; ni < 4; ++ni) {
                int n = wn * 32 + ni * 8 + g;
                bf[ni][0] = Bs[(kO + t) * SGS + n];
                bf[ni][1] = Bs[(kO + t + 4) * SGS + n];
            }
#pragma unroll
            for (int mi = 0; mi < 4; ++mi)
#pragma unroll
                for (int ni = 0; ni < 4; ++ni)
                    mma8(acc[mi][ni], af[mi], bf[ni][0], bf[ni][1]);
        }
        __syncthreads();
    }

    if (TRANSC) {
#pragma unroll
        for (int mi = 0; mi < 4; ++mi) {
            int m = bm * 128 + wm * 64 + mi * 16 + g;
#pragma unroll
            for (int ni = 0; ni < 4; ++ni) {
                int nLoc = bn * 128 + wn * 32 + ni * 8 + 2 * t;
                float b0 = BIAS ? bias[nLoc] : 0.f;
                float b1 = BIAS ? bias[nLoc + 1] : 0.f;
                long base = (long)b * cBatch;
                C[base + (long)(coff + nLoc) * ldc + m]         = acc[mi][ni][0] + b0;
                C[base + (long)(coff + nLoc + 1) * ldc + m]     = acc[mi][ni][1] + b1;
                C[base + (long)(coff + nLoc) * ldc + m + 8]     = acc[mi][ni][2] + b0;
                C[base + (long)(coff + nLoc + 1) * ldc + m + 8] = acc[mi][ni][3] + b1;
            }
        }
    } else {
#pragma unroll
        for (int mi = 0; mi < 4; ++mi) {
            int m = bm * 128 + wm * 64 + mi * 16 + g;
            long r0 = (long)b * cBatch + (long)m * ldc;
            long r1 = r0 + 8L * ldc;
#pragma unroll
            for (int ni = 0; ni < 4; ++ni) {
                int n = bn * 128 + wn * 32 + ni * 8 + 2 * t;
                *(float2*)&C[r0 + n] = make_float2(acc[mi][ni][0], acc[mi][ni][1]);
                *(float2*)&C[r1 + n] = make_float2(acc[mi][ni][2], acc[mi][ni][3]);
            }
        }
    }
}

// ---------------------------------------------------------------------------
// Hi-fi windowed attention: one CTA (128 thr) per (b, window g). warp = head.
// Output written channel-major (houtT: B x 256 x 4096).
// ---------------------------------------------------------------------------
__global__ __launch_bounds__(128)
void hifi_attn(const float* __restrict__ hqkv, float* __restrict__ houtT) {
    __shared__ float sq[4][772];
    int g = blockIdx.x, b = blockIdx.y;
    int gh = g >> 5, gw = g & 31;
    int tid = threadIdx.x;
    int t00 = (gh << 7) + (gw << 1);
    const float* base = hqkv + (long)b * 4096 * 768;
#pragma unroll
    for (int it = 0; it < 6; ++it) {
        int idx = tid + it * 128;
        int n = idx / 192, c4 = idx % 192;
        int t = t00 + ((n >> 1) << 6) + (n & 1);
        *(float4*)&sq[n][c4 * 4] = *(const float4*)(base + (long)t * 768 + c4 * 4);
    }
    __syncthreads();

    int head = tid >> 5, lane = tid & 31;
    int n = (lane >> 2) & 3, m = lane & 3;
    const float* qn = &sq[n][head * 64];
    const float* km = &sq[m][256 + head * 64];
    float s = 0.f;
#pragma unroll
    for (int k = 0; k < 64; ++k) s += qn[k] * km[k];
    s *= 0.125f;

    float mx = fmaxf(s, __shfl_xor_sync(0xffffffffu, s, 1));
    mx = fmaxf(mx, __shfl_xor_sync(0xffffffffu, mx, 2));
    float p = __expf(s - mx);
    float sum = p;
    sum += __shfl_xor_sync(0xffffffffu, sum, 1);
    sum += __shfl_xor_sync(0xffffffffu, sum, 2);
    p = p / sum;

    int no = lane >> 3;
    int d0 = (lane & 7) << 3;
    float o[8];
#pragma unroll
    for (int dd = 0; dd < 8; ++dd) o[dd] = 0.f;
#pragma unroll
    for (int mm = 0; mm < 4; ++mm) {
        float pm = __shfl_sync(0xffffffffu, p, no * 4 + mm);
        const float* vm = &sq[mm][512 + head * 64 + d0];
#pragma unroll
        for (int dd = 0; dd < 8; ++dd) o[dd] += pm * vm[dd];
    }
    int t = t00 + ((no >> 1) << 6) + (no & 1);
    float* ob = houtT + ((long)(b * 256 + head * 64 + d0)) * 4096 + t;
#pragma unroll
    for (int dd = 0; dd < 8; ++dd) ob[(long)dd * 4096] = o[dd];
}

// ---------------------------------------------------------------------------
// Lo-fi flash attention on TF32 mma. CTA = 128 queries x (b, head).
// 8 warps, each warp owns a 16-row band (full n=64). Q fragments in registers
// (loaded once, scale folded). K/V chunks (64 keys) staged tf32, stride 72
// words (== 8 mod 32): conflict-free B-fragment loads. P is moved from the
// S C-layout to the PV A-layout with intra-quad shuffles (no smem, no sync).
// Online softmax state replicated across quad lanes. Output channel-major.
// ---------------------------------------------------------------------------
#define FS 72   // flash smem row stride in words

__global__ __launch_bounds__(256, 1)
void lofi_flash(const float* __restrict__ lq, const float* __restrict__ lkv,
                float* __restrict__ loT) {
    __shared__ unsigned sm[2 * 64 * FS];   // 36,864 B
    unsigned* sK = sm;
    unsigned* sV = sm + 64 * FS;
    int tid = threadIdx.x;
    int warp = tid >> 5, lane = tid & 31;
    int g = lane >> 2, t = lane & 3;
    int qb = blockIdx.x, head = blockIdx.y, b = blockIdx.z;
    int t0 = qb << 7;

    // stage Q tile (128x64), scale folded, tf32
    const float* lqb = lq + ((long)(b * 4096 + t0)) * 256 + head * 64;
#pragma unroll
    for (int it = 0; it < 8; ++it) {
        int idx = tid + it * 256;
        int r = idx >> 4, d4 = (idx & 15) << 2;
        float4 v = *(const float4*)(lqb + r * 256 + d4);
        v.x *= 0.125f; v.y *= 0.125f; v.z *= 0.125f; v.w *= 0.125f;
        *(uint4*)&sm[r * FS + d4] = tf4(v);
    }
    __syncthreads();

    int r0 = warp * 16 + g;
    unsigned qa[8][4];
#pragma unroll
    for (int kk = 0; kk < 8; ++kk) {
        qa[kk][0] = sm[r0 * FS + kk * 8 + t];
        qa[kk][1] = sm[(r0 + 8) * FS + kk * 8 + t];
        qa[kk][2] = sm[r0 * FS + kk * 8 + t + 4];
        qa[kk][3] = sm[(r0 + 8) * FS + kk * 8 + t + 4];
    }
    __syncthreads();

    float oa[8][4];
#pragma unroll
    for (int nj = 0; nj < 8; ++nj)
#pragma unroll
        for (int r = 0; r < 4; ++r) oa[nj][r] = 0.f;
    float m0 = -1e30f, m1 = -1e30f, l0 = 0.f, l1 = 0.f;

    const float* kvb = lkv + (long)b * 524288 + head * 64;

    for (int ch = 0; ch < 16; ++ch) {
#pragma unroll
        for (int it = 0; it < 4; ++it) {
            int idx = tid + it * 256;
            int key = idx >> 4, d4 = (idx & 15) << 2;
            const float* row = kvb + (long)(ch * 64 + key) * 512;
            *(uint4*)&sK[key * FS + d4] = tf4(*(const float4*)(row + d4));
            *(uint4*)&sV[key * FS + d4] = tf4(*(const float4*)(row + 256 + d4));
        }
        __syncthreads();

        // S = Q K^T
        float s[8][4];
#pragma unroll
        for (int nj = 0; nj < 8; ++nj)
#pragma unroll
            for (int r = 0; r < 4; ++r) s[nj][r] = 0.f;
#pragma unroll
        for (int kk = 0; kk < 8; ++kk) {
            int kO = kk * 8;
#pragma unroll
            for (int nj = 0; nj < 8; ++nj) {
                unsigned b0 = sK[(nj * 8 + g) * FS + kO + t];
                unsigned b1 = sK[(nj * 8 + g) * FS + kO + t + 4];
                mma8(s[nj], qa[kk], b0, b1);
            }
        }

        // online softmax: rows r0 (regs 0,1) and r0+8 (regs 2,3)
        float mx0 = -1e30f, mx1 = -1e30f;
#pragma unroll
        for (int nj = 0; nj < 8; ++nj) {
            mx0 = fmaxf(mx0, fmaxf(s[nj][0], s[nj][1]));
            mx1 = fmaxf(mx1, fmaxf(s[nj][2], s[nj][3]));
        }
        mx0 = fmaxf(mx0, __shfl_xor_sync(0xffffffffu, mx0, 1));
        mx0 = fmaxf(mx0, __shfl_xor_sync(0xffffffffu, mx0, 2));
        mx1 = fmaxf(mx1, __shfl_xor_sync(0xffffffffu, mx1, 1));
        mx1 = fmaxf(mx1, __shfl_xor_sync(0xffffffffu, mx1, 2));
        float mn0 = fmaxf(m0, mx0), mn1 = fmaxf(m1, mx1);
        float al0 = __expf(m0 - mn0), al1 = __expf(m1 - mn1);
        float sum0 = 0.f, sum1 = 0.f;
#pragma unroll
        for (int nj = 0; nj < 8; ++nj) {
            s[nj][0] = __expf(s[nj][0] - mn0); sum0 += s[nj][0];
            s[nj][1] = __expf(s[nj][1] - mn0); sum0 += s[nj][1];
            s[nj][2] = __expf(s[nj][2] - mn1); sum1 += s[nj][2];
            s[nj][3] = __expf(s[nj][3] - mn1); sum1 += s[nj][3];
        }
        sum0 += __shfl_xor_sync(0xffffffffu, sum0, 1);
        sum0 += __shfl_xor_sync(0xffffffffu, sum0, 2);
        sum1 += __shfl_xor_sync(0xffffffffu, sum1, 1);
        sum1 += __shfl_xor_sync(0xffffffffu, sum1, 2);
        l0 = l0 * al0 + sum0; m0 = mn0;
        l1 = l1 * al1 + sum1; m1 = mn1;
#pragma unroll
        for (int nj = 0; nj < 8; ++nj) {
            oa[nj][0] *= al0; oa[nj][1] *= al0;
            oa[nj][2] *= al1; oa[nj][3] *= al1;
        }

        // O += P V : P fragments via intra-quad shuffles
        int srcA = (lane & ~3) | (t >> 1);
        int p1 = t & 1;
#pragma unroll
        for (int kk = 0; kk < 8; ++kk) {
            float x0 = __shfl_sync(0xffffffffu, s[kk][0], srcA);
            float x1 = __shfl_sync(0xffffffffu, s[kk][1], srcA);
            float y0 = __shfl_sync(0xffffffffu, s[kk][0], srcA + 2);
            float y1 = __shfl_sync(0xffffffffu, s[kk][1], srcA + 2);
            float z0 = __shfl_sync(0xffffffffu, s[kk][2], srcA);
            float z1 = __shfl_sync(0xffffffffu, s[kk][3], srcA);
            float w0 = __shfl_sync(0xffffffffu, s[kk][2], srcA + 2);
            float w1 = __shfl_sync(0xffffffffu, s[kk][3], srcA + 2);
            unsigned pa[4];
            pa[0] = f2tf(p1 ? x1 : x0);
            pa[2] = f2tf(p1 ? y1 : y0);
            pa[1] = f2tf(p1 ? z1 : z0);
            pa[3] = f2tf(p1 ? w1 : w0);
            int kO = kk * 8;
#pragma unroll
            for (int nj = 0; nj < 8; ++nj) {
                unsigned b0 = sV[(kO + t) * FS + nj * 8 + g];
                unsigned b1 = sV[(kO + t + 4) * FS + nj * 8 + g];
                mma8(oa[nj], pa, b0, b1);
            }
        }
        __syncthreads();
    }

    float inv0 = __frcp_rn(l0), inv1 = __frcp_rn(l1);
#pragma unroll
    for (int nj = 0; nj < 8; ++nj) {
        int col = nj * 8 + 2 * t;
        float* ob = loT + ((long)(b * 256 + head * 64 + col)) * 4096 + t0;
        ob[r0] = oa[nj][0] * inv0;
        ob[4096 + r0] = oa[nj][1] * inv0;
        ob[r0 + 8] = oa[nj][2] * inv1;
        ob[4096 + r0 + 8] = oa[nj][3] * inv1;
    }
}

// ---------------------------------------------------------------------------
extern "C" void kernel_launch(void* const* d_in, const int* in_sizes, int n_in,
                              void* d_out, int out_size) {
    const float* x        = (const float*)d_in[0];
    const float* h_qkv_w  = (const float*)d_in[1];
    const float* h_proj_w = (const float*)d_in[2];
    const float* h_proj_b = (const float*)d_in[3];
    const float* l_q_w    = (const float*)d_in[4];
    const float* l_kv_w   = (const float*)d_in[5];
    const float* l_proj_w = (const float*)d_in[6];
    const float* l_proj_b = (const float*)d_in[7];
    float* out = (float*)d_out;

    float* scratch = nullptr;
    cudaGetSymbolAddress((void**)&scratch, g_scratch);
    float* pooledT = scratch + OFF_POOL;
    float* hqkv    = scratch + OFF_HQKV;
    float* lqv     = scratch + OFF_LQ;
    float* lkv     = scratch + OFF_LKV;
    float* houtT   = scratch + OFF_HOUT;
    float* loT     = scratch + OFF_LOT;

    pool_kernel<<<8192, 256>>>(x, pooledT);

    // hqkv (B,4096,768) = x^T @ h_qkv_w
    tgemm_tn<0, 0><<<dim3(32, 6, NBATCH), 256>>>(
        x, 2097152L, 4096, h_qkv_w, 768, hqkv, 4096L * 768, 768, 0, nullptr, 512);
    // lq (B,4096,256) = x^T @ l_q_w
    tgemm_tn<0, 0><<<dim3(32, 2, NBATCH), 256>>>(
        x, 2097152L, 4096, l_q_w, 256, lqv, 4096L * 256, 256, 0, nullptr, 512);
    // lkv (B,1024,512) = pooled^T @ l_kv_w
    tgemm_tn<0, 0><<<dim3(8, 4, NBATCH), 256>>>(
        pooledT, 524288L, 1024, l_kv_w, 512, lkv, 1024L * 512, 512, 0, nullptr, 512);

    hifi_attn<<<dim3(1024, NBATCH), 128>>>(hqkv, houtT);
    lofi_flash<<<dim3(32, 4, NBATCH), 256>>>(lqv, lkv, loT);

    // out[:, 0:256]  = houtT^T @ h_proj_w + b  (NCHW channel-major)
    tgemm_tn<1, 1><<<dim3(32, 2, NBATCH), 256>>>(
        houtT, 1048576L, 4096, h_proj_w, 256, out, 2097152L, 4096, 0, h_proj_b, 256);
    // out[:, 256:512] = loT^T @ l_proj_w + b
    tgemm_tn<1, 1><<<dim3(32, 2, NBATCH), 256>>>(
        loT, 1048576L, 4096, l_proj_w, 256, out, 2097152L, 4096, 256, l_proj_b, 256);
}

// round 6
// speedup vs baseline: 2.5799x; 1.0925x over previous
#include <cuda_runtime.h>

// ---------------------------------------------------------------------------
// HiLo attention. TF32 tensor cores (mma.m16n8k8), fp32 accumulate.
// cp.async 3-stage pipelines; token-major intermediates; coalesced epilogues.
// ---------------------------------------------------------------------------

#define NBATCH 4

// scratch layout (floats)
#define OFF_POOL  0L                  // pooledT (B,512,1024)
#define OFF_HQKV  2097152L            // hqkv    (B,4096,768)   token-major
#define OFF_LQ    14680064L           // lq      (B,4096,256)   token-major
#define OFF_LKV   18874368L           // lkv     (B,1024,512)   token-major
#define OFF_HOUT  20971520L           // hout    (B,4096,256)   token-major
#define OFF_LOT   25165824L           // lo      (B,4096,256)   token-major
#define SCRATCH_FLOATS 29360128L

__device__ float g_scratch[SCRATCH_FLOATS];

// ---------------------------------------------------------------------------
__device__ __forceinline__ unsigned f2tf(float f) {
    unsigned r;
    asm("cvt.rna.tf32.f32 %0, %1;" : "=r"(r) : "f"(f));
    return r;
}

__device__ __forceinline__ void mma8(float* d, const unsigned* a,
                                     unsigned b0, unsigned b1) {
    asm volatile(
        "mma.sync.aligned.m16n8k8.row.col.f32.tf32.tf32.f32 "
        "{%0,%1,%2,%3}, {%4,%5,%6,%7}, {%8,%9}, {%0,%1,%2,%3};\n"
        : "+f"(d[0]), "+f"(d[1]), "+f"(d[2]), "+f"(d[3])
        : "r"(a[0]), "r"(a[1]), "r"(a[2]), "r"(a[3]), "r"(b0), "r"(b1));
}

__device__ __forceinline__ void cpasync16(void* smem, const void* gmem) {
    unsigned s = (unsigned)__cvta_generic_to_shared(smem);
    asm volatile("cp.async.cg.shared.global [%0], [%1], 16;" :: "r"(s), "l"(gmem));
}
#define CP_COMMIT asm volatile("cp.async.commit_group;")
#define CP_WAIT1  asm volatile("cp.async.wait_group 1;")

// ---------------------------------------------------------------------------
// 2x2 mean pool:  pooledT[b][c][g]
// ---------------------------------------------------------------------------
__global__ __launch_bounds__(256)
void pool_kernel(const float* __restrict__ x, float* __restrict__ pooledT) {
    long idx = (long)blockIdx.x * 256 + threadIdx.x;
    int g = (int)(idx & 1023);
    int c = (int)((idx >> 10) & 511);
    int b = (int)(idx >> 19);
    int gh = g >> 5, gw = g & 31;
    const float* p = x + ((long)(b * 512 + c) << 12) + (gh << 7) + (gw << 1);
    pooledT[idx] = 0.25f * (p[0] + p[1] + p[64] + p[65]);
}

// ---------------------------------------------------------------------------
// TF32 TN GEMM (A stored K-major: K x lda). 128x128 tile, BK=32, 3-stage
// cp.async ring, raw f32 in smem, cvt at fragment load. SGS=136 (conflict-free).
// ---------------------------------------------------------------------------
#define SGS 136
#define TN_STG 8704   // words per stage (As 32*136 + Bs 32*136)
#define TN_SMEM (3 * TN_STG * 4)

template<int TRANSC, int BIAS>
__global__ __launch_bounds__(256)
void tgemm_tn(const float* __restrict__ A, long aBatch, int lda,
              const float* __restrict__ Bw, int ldb,
              float* __restrict__ C, long cBatch, int ldc, int coff,
              const float* __restrict__ bias, int K) {
    extern __shared__ float ts[];
    int tid = threadIdx.x;
    int bm = blockIdx.x, bn = blockIdx.y, b = blockIdx.z;
    const float* Ab = A + (long)b * aBatch + bm * 128;
    const float* Bb = Bw + bn * 128;
    int lk = tid >> 5, lm4 = (tid & 31) << 2;
    int warp = tid >> 5, lane = tid & 31;
    int wm = warp >> 2, wn = warp & 3;
    int g = lane >> 2, t = lane & 3;

    float acc[4][4][4];
#pragma unroll
    for (int i = 0; i < 4; i++)
#pragma unroll
        for (int j = 0; j < 4; j++)
#pragma unroll
            for (int r = 0; r < 4; r++) acc[i][j][r] = 0.f;

    int KT = K >> 5;
    auto issue = [&](int st) {
        float* As = ts + (st % 3) * TN_STG;
        float* Bs = As + 32 * SGS;
#pragma unroll
        for (int it = 0; it < 4; ++it) {
            int k = lk + 8 * it;
            cpasync16(&As[k * SGS + lm4], Ab + (long)(st * 32 + k) * lda + lm4);
            cpasync16(&Bs[k * SGS + lm4], Bb + (long)(st * 32 + k) * ldb + lm4);
        }
    };
    issue(0); CP_COMMIT;
    issue(1); CP_COMMIT;

    for (int kt = 0; kt < KT; ++kt) {
        CP_WAIT1;
        __syncthreads();
        if (kt + 2 < KT) issue(kt + 2);
        CP_COMMIT;
        const float* As = ts + (kt % 3) * TN_STG;
        const float* Bs = As + 32 * SGS;
#pragma unroll
        for (int kk = 0; kk < 4; ++kk) {
            int kO = kk * 8;
            unsigned af[4][4], bf[4][2];
#pragma unroll
            for (int mi = 0; mi < 4; ++mi) {
                int m = wm * 64 + mi * 16 + g;
                af[mi][0] = f2tf(As[(kO + t) * SGS + m]);
                af[mi][1] = f2tf(As[(kO + t) * SGS + m + 8]);
                af[mi][2] = f2tf(As[(kO + t + 4) * SGS + m]);
                af[mi][3] = f2tf(As[(kO + t + 4) * SGS + m + 8]);
            }
#pragma unroll
            for (int ni = 0; ni < 4; ++ni) {
                int n = wn * 32 + ni * 8 + g;
                bf[ni][0] = f2tf(Bs[(kO + t) * SGS + n]);
                bf[ni][1] = f2tf(Bs[(kO + t + 4) * SGS + n]);
            }
#pragma unroll
            for (int mi = 0; mi < 4; ++mi)
#pragma unroll
                for (int ni = 0; ni < 4; ++ni)
                    mma8(acc[mi][ni], af[mi], bf[ni][0], bf[ni][1]);
        }
    }

    if (TRANSC) {
#pragma unroll
        for (int mi = 0; mi < 4; ++mi) {
            int m = bm * 128 + wm * 64 + mi * 16 + g;
#pragma unroll
            for (int ni = 0; ni < 4; ++ni) {
                int nLoc = bn * 128 + wn * 32 + ni * 8 + 2 * t;
                float b0 = BIAS ? bias[nLoc] : 0.f;
                float b1 = BIAS ? bias[nLoc + 1] : 0.f;
                long base = (long)b * cBatch;
                C[base + (long)(coff + nLoc) * ldc + m]         = acc[mi][ni][0] + b0;
                C[base + (long)(coff + nLoc + 1) * ldc + m]     = acc[mi][ni][1] + b1;
                C[base + (long)(coff + nLoc) * ldc + m + 8]     = acc[mi][ni][2] + b0;
                C[base + (long)(coff + nLoc + 1) * ldc + m + 8] = acc[mi][ni][3] + b1;
            }
        }
    } else {
#pragma unroll
        for (int mi = 0; mi < 4; ++mi) {
            int m = bm * 128 + wm * 64 + mi * 16 + g;
            long r0 = (long)b * cBatch + (long)m * ldc;
            long r1 = r0 + 8L * ldc;
#pragma unroll
            for (int ni = 0; ni < 4; ++ni) {
                int n = bn * 128 + wn * 32 + ni * 8 + 2 * t;
                *(float2*)&C[r0 + n] = make_float2(acc[mi][ni][0], acc[mi][ni][1]);
                *(float2*)&C[r1 + n] = make_float2(acc[mi][ni][2], acc[mi][ni][3]);
            }
        }
    }
}

// ---------------------------------------------------------------------------
// TF32 NT GEMM (A row-major: M x lda, lda = K). As stored [m][36] (conflict-
// free: bank = (4m+k)&31). Same pipeline/epilogue as TN.
// ---------------------------------------------------------------------------
#define NTA 36
#define NT_STG (128 * NTA + 32 * SGS)   // 4608 + 4352 = 8960 words
#define NT_SMEM (3 * NT_STG * 4)

template<int TRANSC, int BIAS>
__global__ __launch_bounds__(256)
void tgemm_nt(const float* __restrict__ A, long aBatch, int lda,
              const float* __restrict__ Bw, int ldb,
              float* __restrict__ C, long cBatch, int ldc, int coff,
              const float* __restrict__ bias, int K) {
    extern __shared__ float ns[];
    int tid = threadIdx.x;
    int bm = blockIdx.x, bn = blockIdx.y, b = blockIdx.z;
    const float* Ab = A + (long)b * aBatch + (long)(bm * 128) * lda;
    const float* Bb = Bw + bn * 128;
    int am = tid & 127, ah = tid >> 7;
    int lk = tid >> 5, lm4 = (tid & 31) << 2;
    int warp = tid >> 5, lane = tid & 31;
    int wm = warp >> 2, wn = warp & 3;
    int g = lane >> 2, t = lane & 3;

    float acc[4][4][4];
#pragma unroll
    for (int i = 0; i < 4; i++)
#pragma unroll
        for (int j = 0; j < 4; j++)
#pragma unroll
            for (int r = 0; r < 4; r++) acc[i][j][r] = 0.f;

    int KT = K >> 5;
    auto issue = [&](int st) {
        float* As = ns + (st % 3) * NT_STG;
        float* Bs = As + 128 * NTA;
        const float* Asrc = Ab + (long)am * lda + st * 32 + ah * 16;
#pragma unroll
        for (int j = 0; j < 4; ++j)
            cpasync16(&As[am * NTA + ah * 16 + j * 4], Asrc + j * 4);
#pragma unroll
        for (int it = 0; it < 4; ++it) {
            int k = lk + 8 * it;
            cpasync16(&Bs[k * SGS + lm4], Bb + (long)(st * 32 + k) * ldb + lm4);
        }
    };
    issue(0); CP_COMMIT;
    issue(1); CP_COMMIT;

    for (int kt = 0; kt < KT; ++kt) {
        CP_WAIT1;
        __syncthreads();
        if (kt + 2 < KT) issue(kt + 2);
        CP_COMMIT;
        const float* As = ns + (kt % 3) * NT_STG;
        const float* Bs = As + 128 * NTA;
#pragma unroll
        for (int kk = 0; kk < 4; ++kk) {
            int kO = kk * 8;
            unsigned af[4][4], bf[4][2];
#pragma unroll
            for (int mi = 0; mi < 4; ++mi) {
                int m = wm * 64 + mi * 16 + g;
                af[mi][0] = f2tf(As[m * NTA + kO + t]);
                af[mi][1] = f2tf(As[(m + 8) * NTA + kO + t]);
                af[mi][2] = f2tf(As[m * NTA + kO + t + 4]);
                af[mi][3] = f2tf(As[(m + 8) * NTA + kO + t + 4]);
            }
#pragma unroll
            for (int ni = 0; ni < 4; ++ni) {
                int n = wn * 32 + ni * 8 + g;
                bf[ni][0] = f2tf(Bs[(kO + t) * SGS + n]);
                bf[ni][1] = f2tf(Bs[(kO + t + 4) * SGS + n]);
            }
#pragma unroll
            for (int mi = 0; mi < 4; ++mi)
#pragma unroll
                for (int ni = 0; ni < 4; ++ni)
                    mma8(acc[mi][ni], af[mi], bf[ni][0], bf[ni][1]);
        }
    }

    if (TRANSC) {
#pragma unroll
        for (int mi = 0; mi < 4; ++mi) {
            int m = bm * 128 + wm * 64 + mi * 16 + g;
#pragma unroll
            for (int ni = 0; ni < 4; ++ni) {
                int nLoc = bn * 128 + wn * 32 + ni * 8 + 2 * t;
                float b0 = BIAS ? bias[nLoc] : 0.f;
                float b1 = BIAS ? bias[nLoc + 1] : 0.f;
                long base = (long)b * cBatch;
                C[base + (long)(coff + nLoc) * ldc + m]         = acc[mi][ni][0] + b0;
                C[base + (long)(coff + nLoc + 1) * ldc + m]     = acc[mi][ni][1] + b1;
                C[base + (long)(coff + nLoc) * ldc + m + 8]     = acc[mi][ni][2] + b0;
                C[base + (long)(coff + nLoc + 1) * ldc + m + 8] = acc[mi][ni][3] + b1;
            }
        }
    } else {
#pragma unroll
        for (int mi = 0; mi < 4; ++mi) {
            int m = bm * 128 + wm * 64 + mi * 16 + g;
            long r0 = (long)b * cBatch + (long)m * ldc;
            long r1 = r0 + 8L * ldc;
#pragma unroll
            for (int ni = 0; ni < 4; ++ni) {
                int n = bn * 128 + wn * 32 + ni * 8 + 2 * t;
                *(float2*)&C[r0 + n] = make_float2(acc[mi][ni][0], acc[mi][ni][1]);
                *(float2*)&C[r1 + n] = make_float2(acc[mi][ni][2], acc[mi][ni][3]);
            }
        }
    }
}

// ---------------------------------------------------------------------------
// Hi-fi windowed attention. CTA (128 thr) per (b, window). warp = head.
// Output staged in smem, written TOKEN-MAJOR (hout: B x 4096 x 256), coalesced.
// ---------------------------------------------------------------------------
__global__ __launch_bounds__(128)
void hifi_attn(const float* __restrict__ hqkv, float* __restrict__ hout) {
    __shared__ float sq[4][772];
    __shared__ float sto[4][260];
    int g = blockIdx.x, b = blockIdx.y;
    int gh = g >> 5, gw = g & 31;
    int tid = threadIdx.x;
    int t00 = (gh << 7) + (gw << 1);
    const float* base = hqkv + (long)b * 4096 * 768;
#pragma unroll
    for (int it = 0; it < 6; ++it) {
        int idx = tid + it * 128;
        int n = idx / 192, c4 = idx % 192;
        int t = t00 + ((n >> 1) << 6) + (n & 1);
        *(float4*)&sq[n][c4 * 4] = *(const float4*)(base + (long)t * 768 + c4 * 4);
    }
    __syncthreads();

    int head = tid >> 5, lane = tid & 31;
    int n = (lane >> 2) & 3, m = lane & 3;
    const float* qn = &sq[n][head * 64];
    const float* km = &sq[m][256 + head * 64];
    float s = 0.f;
#pragma unroll
    for (int k = 0; k < 64; ++k) s += qn[k] * km[k];
    s *= 0.125f;

    float mx = fmaxf(s, __shfl_xor_sync(0xffffffffu, s, 1));
    mx = fmaxf(mx, __shfl_xor_sync(0xffffffffu, mx, 2));
    float p = __expf(s - mx);
    float sum = p;
    sum += __shfl_xor_sync(0xffffffffu, sum, 1);
    sum += __shfl_xor_sync(0xffffffffu, sum, 2);
    p = p / sum;

    int no = lane >> 3;
    int d0 = (lane & 7) << 3;
    float o[8];
#pragma unroll
    for (int dd = 0; dd < 8; ++dd) o[dd] = 0.f;
#pragma unroll
    for (int mm = 0; mm < 4; ++mm) {
        float pm = __shfl_sync(0xffffffffu, p, no * 4 + mm);
        const float* vm = &sq[mm][512 + head * 64 + d0];
#pragma unroll
        for (int dd = 0; dd < 8; ++dd) o[dd] += pm * vm[dd];
    }
    int c0 = head * 64 + d0;
    *(float4*)&sto[no][c0]     = make_float4(o[0], o[1], o[2], o[3]);
    *(float4*)&sto[no][c0 + 4] = make_float4(o[4], o[5], o[6], o[7]);
    __syncthreads();

#pragma unroll
    for (int it = 0; it < 2; ++it) {
        int idx = tid + it * 128;               // 256 float4 total
        int tok = idx >> 6, c4 = (idx & 63) << 2;
        int t = t00 + ((tok >> 1) << 6) + (tok & 1);
        *(float4*)(hout + ((long)b * 4096 + t) * 256 + c4) = *(float4*)&sto[tok][c4];
    }
}

// ---------------------------------------------------------------------------
// Lo-fi flash attention, TF32 mma. CTA = 128 queries x (b, head). 8 warps,
// warp = 16-row band. cp.async 3-stage KV ring (raw f32, cvt at consume).
// K stride 68, V stride 72 -> both fragment patterns conflict-free.
// Output staged in smem, written TOKEN-MAJOR (lo: B x 4096 x 256).
// ---------------------------------------------------------------------------
#define FKS 68
#define FVS 72
#define F_STG (64 * FKS + 64 * FVS)   // 8960 words
#define F_SMEM (3 * F_STG * 4)

__global__ __launch_bounds__(256, 1)
void lofi_flash(const float* __restrict__ lq, const float* __restrict__ lkv,
                float* __restrict__ lo) {
    extern __shared__ float fs[];
    int tid = threadIdx.x;
    int warp = tid >> 5, lane = tid & 31;
    int g = lane >> 2, t = lane & 3;
    int qb = blockIdx.x, head = blockIdx.y, b = blockIdx.z;
    int t0 = qb << 7;

    // stage Q (128x64, scaled, f32) into stage-0 region; frags to regs
    const float* lqb = lq + ((long)(b * 4096 + t0)) * 256 + head * 64;
#pragma unroll
    for (int it = 0; it < 8; ++it) {
        int idx = tid + it * 256;
        int r = idx >> 4, d4 = (idx & 15) << 2;
        float4 v = *(const float4*)(lqb + r * 256 + d4);
        v.x *= 0.125f; v.y *= 0.125f; v.z *= 0.125f; v.w *= 0.125f;
        *(float4*)&fs[r * FKS + d4] = v;
    }
    __syncthreads();

    int r0 = warp * 16 + g;
    unsigned qa[8][4];
#pragma unroll
    for (int kk = 0; kk < 8; ++kk) {
        qa[kk][0] = f2tf(fs[r0 * FKS + kk * 8 + t]);
        qa[kk][1] = f2tf(fs[(r0 + 8) * FKS + kk * 8 + t]);
        qa[kk][2] = f2tf(fs[r0 * FKS + kk * 8 + t + 4]);
        qa[kk][3] = f2tf(fs[(r0 + 8) * FKS + kk * 8 + t + 4]);
    }
    __syncthreads();

    float oa[8][4];
#pragma unroll
    for (int nj = 0; nj < 8; ++nj)
#pragma unroll
        for (int r = 0; r < 4; ++r) oa[nj][r] = 0.f;
    float m0 = -1e30f, m1 = -1e30f, l0 = 0.f, l1 = 0.f;

    const float* kvb = lkv + (long)b * 524288 + head * 64;

    auto issue = [&](int st) {
        float* bK = fs + (st % 3) * F_STG;
        float* bV = bK + 64 * FKS;
#pragma unroll
        for (int it = 0; it < 4; ++it) {
            int idx = tid + it * 256;
            int key = idx >> 4, d4 = (idx & 15) << 2;
            const float* row = kvb + (long)(st * 64 + key) * 512;
            cpasync16(&bK[key * FKS + d4], row + d4);
            cpasync16(&bV[key * FVS + d4], row + 256 + d4);
        }
    };
    issue(0); CP_COMMIT;
    issue(1); CP_COMMIT;

    for (int ch = 0; ch < 16; ++ch) {
        CP_WAIT1;
        __syncthreads();
        if (ch + 2 < 16) issue(ch + 2);
        CP_COMMIT;
        const float* sK = fs + (ch % 3) * F_STG;
        const float* sV = sK + 64 * FKS;

        // S = Q K^T
        float s[8][4];
#pragma unroll
        for (int nj = 0; nj < 8; ++nj)
#pragma unroll
            for (int r = 0; r < 4; ++r) s[nj][r] = 0.f;
#pragma unroll
        for (int kk = 0; kk < 8; ++kk) {
            int kO = kk * 8;
#pragma unroll
            for (int nj = 0; nj < 8; ++nj) {
                unsigned b0 = f2tf(sK[(nj * 8 + g) * FKS + kO + t]);
                unsigned b1 = f2tf(sK[(nj * 8 + g) * FKS + kO + t + 4]);
                mma8(s[nj], qa[kk], b0, b1);
            }
        }

        // online softmax (rows r0 -> regs 0,1 ; r0+8 -> regs 2,3)
        float mx0 = -1e30f, mx1 = -1e30f;
#pragma unroll
        for (int nj = 0; nj < 8; ++nj) {
            mx0 = fmaxf(mx0, fmaxf(s[nj][0], s[nj][1]));
            mx1 = fmaxf(mx1, fmaxf(s[nj][2], s[nj][3]));
        }
        mx0 = fmaxf(mx0, __shfl_xor_sync(0xffffffffu, mx0, 1));
        mx0 = fmaxf(mx0, __shfl_xor_sync(0xffffffffu, mx0, 2));
        mx1 = fmaxf(mx1, __shfl_xor_sync(0xffffffffu, mx1, 1));
        mx1 = fmaxf(mx1, __shfl_xor_sync(0xffffffffu, mx1, 2));
        float mn0 = fmaxf(m0, mx0), mn1 = fmaxf(m1, mx1);
        float al0 = __expf(m0 - mn0), al1 = __expf(m1 - mn1);
        float sum0 = 0.f, sum1 = 0.f;
#pragma unroll
        for (int nj = 0; nj < 8; ++nj) {
            s[nj][0] = __expf(s[nj][0] - mn0); sum0 += s[nj][0];
            s[nj][1] = __expf(s[nj][1] - mn0); sum0 += s[nj][1];
            s[nj][2] = __expf(s[nj][2] - mn1); sum1 += s[nj][2];
            s[nj][3] = __expf(s[nj][3] - mn1); sum1 += s[nj][3];
        }
        sum0 += __shfl_xor_sync(0xffffffffu, sum0, 1);
        sum0 += __shfl_xor_sync(0xffffffffu, sum0, 2);
        sum1 += __shfl_xor_sync(0xffffffffu, sum1, 1);
        sum1 += __shfl_xor_sync(0xffffffffu, sum1, 2);
        l0 = l0 * al0 + sum0; m0 = mn0;
        l1 = l1 * al1 + sum1; m1 = mn1;
#pragma unroll
        for (int nj = 0; nj < 8; ++nj) {
            oa[nj][0] *= al0; oa[nj][1] *= al0;
            oa[nj][2] *= al1; oa[nj][3] *= al1;
        }

        // O += P V : P fragments via intra-quad shuffles
        int srcA = (lane & ~3) | (t >> 1);
        int p1 = t & 1;
#pragma unroll
        for (int kk = 0; kk < 8; ++kk) {
            float x0 = __shfl_sync(0xffffffffu, s[kk][0], srcA);
            float x1 = __shfl_sync(0xffffffffu, s[kk][1], srcA);
            float y0 = __shfl_sync(0xffffffffu, s[kk][0], srcA + 2);
            float y1 = __shfl_sync(0xffffffffu, s[kk][1], srcA + 2);
            float z0 = __shfl_sync(0xffffffffu, s[kk][2], srcA);
            float z1 = __shfl_sync(0xffffffffu, s[kk][3], srcA);
            float w0 = __shfl_sync(0xffffffffu, s[kk][2], srcA + 2);
            float w1 = __shfl_sync(0xffffffffu, s[kk][3], srcA + 2);
            unsigned pa[4];
            pa[0] = f2tf(p1 ? x1 : x0);
            pa[2] = f2tf(p1 ? y1 : y0);
            pa[1] = f2tf(p1 ? z1 : z0);
            pa[3] = f2tf(p1 ? w1 : w0);
            int kO = kk * 8;
#pragma unroll
            for (int nj = 0; nj < 8; ++nj) {
                unsigned b0 = f2tf(sV[(kO + t) * FVS + nj * 8 + g]);
                unsigned b1 = f2tf(sV[(kO + t + 4) * FVS + nj * 8 + g]);
                mma8(oa[nj], pa, b0, b1);
            }
        }
    }

    // epilogue: stage 128x64 head-slice in smem, write token-major coalesced
    __syncthreads();
    float inv0 = __frcp_rn(l0), inv1 = __frcp_rn(l1);
#pragma unroll
    for (int nj = 0; nj < 8; ++nj) {
        int c = nj * 8 + 2 * t;
        fs[r0 * FKS + c]           = oa[nj][0] * inv0;
        fs[r0 * FKS + c + 1]       = oa[nj][1] * inv0;
        fs[(r0 + 8) * FKS + c]     = oa[nj][2] * inv1;
        fs[(r0 + 8) * FKS + c + 1] = oa[nj][3] * inv1;
    }
    __syncthreads();
#pragma unroll
    for (int it = 0; it < 8; ++it) {
        int idx = tid + it * 256;             // 2048 float4
        int r = idx >> 4, c4 = (idx & 15) << 2;
        *(float4*)(lo + ((long)(b * 4096 + t0 + r)) * 256 + head * 64 + c4) =
            *(float4*)&fs[r * FKS + c4];
    }
}

// ---------------------------------------------------------------------------
extern "C" void kernel_launch(void* const* d_in, const int* in_sizes, int n_in,
                              void* d_out, int out_size) {
    const float* x        = (const float*)d_in[0];
    const float* h_qkv_w  = (const float*)d_in[1];
    const float* h_proj_w = (const float*)d_in[2];
    const float* h_proj_b = (const float*)d_in[3];
    const float* l_q_w    = (const float*)d_in[4];
    const float* l_kv_w   = (const float*)d_in[5];
    const float* l_proj_w = (const float*)d_in[6];
    const float* l_proj_b = (const float*)d_in[7];
    float* out = (float*)d_out;

    float* scratch = nullptr;
    cudaGetSymbolAddress((void**)&scratch, g_scratch);
    float* pooledT = scratch + OFF_POOL;
    float* hqkv    = scratch + OFF_HQKV;
    float* lqv     = scratch + OFF_LQ;
    float* lkv     = scratch + OFF_LKV;
    float* hout    = scratch + OFF_HOUT;
    float* lov     = scratch + OFF_LOT;

    cudaFuncSetAttribute(tgemm_tn<0, 0>,
                         cudaFuncAttributeMaxDynamicSharedMemorySize, TN_SMEM);
    cudaFuncSetAttribute(tgemm_nt<1, 1>,
                         cudaFuncAttributeMaxDynamicSharedMemorySize, NT_SMEM);
    cudaFuncSetAttribute(lofi_flash,
                         cudaFuncAttributeMaxDynamicSharedMemorySize, F_SMEM);

    pool_kernel<<<8192, 256>>>(x, pooledT);

    // hqkv (B,4096,768) = x^T @ h_qkv_w
    tgemm_tn<0, 0><<<dim3(32, 6, NBATCH), 256, TN_SMEM>>>(
        x, 2097152L, 4096, h_qkv_w, 768, hqkv, 4096L * 768, 768, 0, nullptr, 512);
    // lq (B,4096,256) = x^T @ l_q_w
    tgemm_tn<0, 0><<<dim3(32, 2, NBATCH), 256, TN_SMEM>>>(
        x, 2097152L, 4096, l_q_w, 256, lqv, 4096L * 256, 256, 0, nullptr, 512);
    // lkv (B,1024,512) = pooled^T @ l_kv_w
    tgemm_tn<0, 0><<<dim3(8, 4, NBATCH), 256, TN_SMEM>>>(
        pooledT, 524288L, 1024, l_kv_w, 512, lkv, 1024L * 512, 512, 0, nullptr, 512);

    hifi_attn<<<dim3(1024, NBATCH), 128>>>(hqkv, hout);
    lofi_flash<<<dim3(32, 4, NBATCH), 256, F_SMEM>>>(lqv, lkv, lov);

    // out[:, 0:256]  = hout @ h_proj_w + b   (NCHW channel-major epilogue)
    tgemm_nt<1, 1><<<dim3(32, 2, NBATCH), 256, NT_SMEM>>>(
        hout, 1048576L, 256, h_proj_w, 256, out, 2097152L, 4096, 0, h_proj_b, 256);
    // out[:, 256:512] = lo @ l_proj_w + b
    tgemm_nt<1, 1><<<dim3(32, 2, NBATCH), 256, NT_SMEM>>>(
        lov, 1048576L, 256, l_proj_w, 256, out, 2097152L, 4096, 256, l_proj_b, 256);
}

// round 10
// speedup vs baseline: 2.5809x; 1.0004x over previous
#include <cuda_runtime.h>

// ---------------------------------------------------------------------------
// HiLo attention. TF32 tensor cores (mma.m16n8k8), fp32 accumulate.
// cp.async 3-stage pipelines; token-major intermediates; coalesced epilogues.
// ---------------------------------------------------------------------------

#define NBATCH 4

// scratch layout (floats)
#define OFF_POOL  0L                  // pooledT (B,512,1024)
#define OFF_HQKV  2097152L            // hqkv    (B,4096,768)   token-major
#define OFF_LQ    14680064L           // lq      (B,4096,256)   token-major
#define OFF_LKV   18874368L           // lkv     (B,1024,512)   token-major
#define OFF_HOUT  20971520L           // hout    (B,4096,256)   token-major
#define OFF_LOT   25165824L           // lo      (B,4096,256)   token-major
#define SCRATCH_FLOATS 29360128L

__device__ float g_scratch[SCRATCH_FLOATS];

// ---------------------------------------------------------------------------
__device__ __forceinline__ unsigned f2tf(float f) {
    unsigned r;
    asm("cvt.rna.tf32.f32 %0, %1;" : "=r"(r) : "f"(f));
    return r;
}

__device__ __forceinline__ void mma8(float* d, const unsigned* a,
                                     unsigned b0, unsigned b1) {
    asm volatile(
        "mma.sync.aligned.m16n8k8.row.col.f32.tf32.tf32.f32 "
        "{%0,%1,%2,%3}, {%4,%5,%6,%7}, {%8,%9}, {%0,%1,%2,%3};\n"
        : "+f"(d[0]), "+f"(d[1]), "+f"(d[2]), "+f"(d[3])
        : "r"(a[0]), "r"(a[1]), "r"(a[2]), "r"(a[3]), "r"(b0), "r"(b1));
}

__device__ __forceinline__ void cpasync16(void* smem, const void* gmem) {
    unsigned s = (unsigned)__cvta_generic_to_shared(smem);
    asm volatile("cp.async.cg.shared.global [%0], [%1], 16;" :: "r"(s), "l"(gmem));
}
#define CP_COMMIT asm volatile("cp.async.commit_group;")
#define CP_WAIT1  asm volatile("cp.async.wait_group 1;")

// ---------------------------------------------------------------------------
// 2x2 mean pool:  pooledT[b][c][g]
// ---------------------------------------------------------------------------
__global__ __launch_bounds__(256)
void pool_kernel(const float* __restrict__ x, float* __restrict__ pooledT) {
    long idx = (long)blockIdx.x * 256 + threadIdx.x;
    int g = (int)(idx & 1023);
    int c = (int)((idx >> 10) & 511);
    int b = (int)(idx >> 19);
    int gh = g >> 5, gw = g & 31;
    const float* p = x + ((long)(b * 512 + c) << 12) + (gh << 7) + (gw << 1);
    pooledT[idx] = 0.25f * (p[0] + p[1] + p[64] + p[65]);
}

// ---------------------------------------------------------------------------
// TF32 TN GEMM (A stored K-major: K x lda). 128x128 tile, BK=32, 3-stage
// cp.async ring, raw f32 in smem, cvt at fragment load. SGS=136 (conflict-free).
// ---------------------------------------------------------------------------
#define SGS 136
#define TN_STG 8704   // words per stage (As 32*136 + Bs 32*136)
#define TN_SMEM (3 * TN_STG * 4)

template<int TRANSC, int BIAS>
__global__ __launch_bounds__(256)
void tgemm_tn(const float* __restrict__ A, long aBatch, int lda,
              const float* __restrict__ Bw, int ldb,
              float* __restrict__ C, long cBatch, int ldc, int coff,
              const float* __restrict__ bias, int K) {
    extern __shared__ float ts[];
    int tid = threadIdx.x;
    int bm = blockIdx.x, bn = blockIdx.y, b = blockIdx.z;
    const float* Ab = A + (long)b * aBatch + bm * 128;
    const float* Bb = Bw + bn * 128;
    int lk = tid >> 5, lm4 = (tid & 31) << 2;
    int warp = tid >> 5, lane = tid & 31;
    int wm = warp >> 2, wn = warp & 3;
    int g = lane >> 2, t = lane & 3;

    float acc[4][4][4];
#pragma unroll
    for (int i = 0; i < 4; i++)
#pragma unroll
        for (int j = 0; j < 4; j++)
#pragma unroll
            for (int r = 0; r < 4; r++) acc[i][j][r] = 0.f;

    int KT = K >> 5;
    auto issue = [&](int st) {
        float* As = ts + (st % 3) * TN_STG;
        float* Bs = As + 32 * SGS;
#pragma unroll
        for (int it = 0; it < 4; ++it) {
            int k = lk + 8 * it;
            cpasync16(&As[k * SGS + lm4], Ab + (long)(st * 32 + k) * lda + lm4);
            cpasync16(&Bs[k * SGS + lm4], Bb + (long)(st * 32 + k) * ldb + lm4);
        }
    };
    issue(0); CP_COMMIT;
    issue(1); CP_COMMIT;

    for (int kt = 0; kt < KT; ++kt) {
        CP_WAIT1;
        __syncthreads();
        if (kt + 2 < KT) issue(kt + 2);
        CP_COMMIT;
        const float* As = ts + (kt % 3) * TN_STG;
        const float* Bs = As + 32 * SGS;
#pragma unroll
        for (int kk = 0; kk < 4; ++kk) {
            int kO = kk * 8;
            unsigned af[4][4], bf[4][2];
#pragma unroll
            for (int mi = 0; mi < 4; ++mi) {
                int m = wm * 64 + mi * 16 + g;
                af[mi][0] = f2tf(As[(kO + t) * SGS + m]);
                af[mi][1] = f2tf(As[(kO + t) * SGS + m + 8]);
                af[mi][2] = f2tf(As[(kO + t + 4) * SGS + m]);
                af[mi][3] = f2tf(As[(kO + t + 4) * SGS + m + 8]);
            }
#pragma unroll
            for (int ni = 0; ni < 4; ++ni) {
                int n = wn * 32 + ni * 8 + g;
                bf[ni][0] = f2tf(Bs[(kO + t) * SGS + n]);
                bf[ni][1] = f2tf(Bs[(kO + t + 4) * SGS + n]);
            }
#pragma unroll
            for (int mi = 0; mi < 4; ++mi)
#pragma unroll
                for (int ni = 0; ni < 4; ++ni)
                    mma8(acc[mi][ni], af[mi], bf[ni][0], bf[ni][1]);
        }
    }

    if (TRANSC) {
#pragma unroll
        for (int mi = 0; mi < 4; ++mi) {
            int m = bm * 128 + wm * 64 + mi * 16 + g;
#pragma unroll
            for (int ni = 0; ni < 4; ++ni) {
                int nLoc = bn * 128 + wn * 32 + ni * 8 + 2 * t;
                float b0 = BIAS ? bias[nLoc] : 0.f;
                float b1 = BIAS ? bias[nLoc + 1] : 0.f;
                long base = (long)b * cBatch;
                C[base + (long)(coff + nLoc) * ldc + m]         = acc[mi][ni][0] + b0;
                C[base + (long)(coff + nLoc + 1) * ldc + m]     = acc[mi][ni][1] + b1;
                C[base + (long)(coff + nLoc) * ldc + m + 8]     = acc[mi][ni][2] + b0;
                C[base + (long)(coff + nLoc + 1) * ldc + m + 8] = acc[mi][ni][3] + b1;
            }
        }
    } else {
#pragma unroll
        for (int mi = 0; mi < 4; ++mi) {
            int m = bm * 128 + wm * 64 + mi * 16 + g;
            long r0 = (long)b * cBatch + (long)m * ldc;
            long r1 = r0 + 8L * ldc;
#pragma unroll
            for (int ni = 0; ni < 4; ++ni) {
                int n = bn * 128 + wn * 32 + ni * 8 + 2 * t;
                *(float2*)&C[r0 + n] = make_float2(acc[mi][ni][0], acc[mi][ni][1]);
                *(float2*)&C[r1 + n] = make_float2(acc[mi][ni][2], acc[mi][ni][3]);
            }
        }
    }
}

// ---------------------------------------------------------------------------
// TF32 NT GEMM (A row-major: M x lda, lda = K). As stored [m][36] (conflict-
// free: bank = (4m+k)&31). Same pipeline/epilogue as TN.
// ---------------------------------------------------------------------------
#define NTA 36
#define NT_STG (128 * NTA + 32 * SGS)   // 4608 + 4352 = 8960 words
#define NT_SMEM (3 * NT_STG * 4)

template<int TRANSC, int BIAS>
__global__ __launch_bounds__(256)
void tgemm_nt(const float* __restrict__ A, long aBatch, int lda,
              const float* __restrict__ Bw, int ldb,
              float* __restrict__ C, long cBatch, int ldc, int coff,
              const float* __restrict__ bias, int K) {
    extern __shared__ float ns[];
    int tid = threadIdx.x;
    int bm = blockIdx.x, bn = blockIdx.y, b = blockIdx.z;
    const float* Ab = A + (long)b * aBatch + (long)(bm * 128) * lda;
    const float* Bb = Bw + bn * 128;
    int am = tid & 127, ah = tid >> 7;
    int lk = tid >> 5, lm4 = (tid & 31) << 2;
    int warp = tid >> 5, lane = tid & 31;
    int wm = warp >> 2, wn = warp & 3;
    int g = lane >> 2, t = lane & 3;

    float acc[4][4][4];
#pragma unroll
    for (int i = 0; i < 4; i++)
#pragma unroll
        for (int j = 0; j < 4; j++)
#pragma unroll
            for (int r = 0; r < 4; r++) acc[i][j][r] = 0.f;

    int KT = K >> 5;
    auto issue = [&](int st) {
        float* As = ns + (st % 3) * NT_STG;
        float* Bs = As + 128 * NTA;
        const float* Asrc = Ab + (long)am * lda + st * 32 + ah * 16;
#pragma unroll
        for (int j = 0; j < 4; ++j)
            cpasync16(&As[am * NTA + ah * 16 + j * 4], Asrc + j * 4);
#pragma unroll
        for (int it = 0; it < 4; ++it) {
            int k = lk + 8 * it;
            cpasync16(&Bs[k * SGS + lm4], Bb + (long)(st * 32 + k) * ldb + lm4);
        }
    };
    issue(0); CP_COMMIT;
    issue(1); CP_COMMIT;

    for (int kt = 0; kt < KT; ++kt) {
        CP_WAIT1;
        __syncthreads();
        if (kt + 2 < KT) issue(kt + 2);
        CP_COMMIT;
        const float* As = ns + (kt % 3) * NT_STG;
        const float* Bs = As + 128 * NTA;
#pragma unroll
        for (int kk = 0; kk < 4; ++kk) {
            int kO = kk * 8;
            unsigned af[4][4], bf[4][2];
#pragma unroll
            for (int mi = 0; mi < 4; ++mi) {
                int m = wm * 64 + mi * 16 + g;
                af[mi][0] = f2tf(As[m * NTA + kO + t]);
                af[mi][1] = f2tf(As[(m + 8) * NTA + kO + t]);
                af[mi][2] = f2tf(As[m * NTA + kO + t + 4]);
                af[mi][3] = f2tf(As[(m + 8) * NTA + kO + t + 4]);
            }
#pragma unroll
            for (int ni = 0; ni < 4; ++ni) {
                int n = wn * 32 + ni * 8 + g;
                bf[ni][0] = f2tf(Bs[(kO + t) * SGS + n]);
                bf[ni][1] = f2tf(Bs[(kO + t + 4) * SGS + n]);
            }
#pragma unroll
            for (int mi = 0; mi < 4; ++mi)
#pragma unroll
                for (int ni = 0; ni < 4; ++ni)
                    mma8(acc[mi][ni], af[mi], bf[ni][0], bf[ni][1]);
        }
    }

    if (TRANSC) {
#pragma unroll
        for (int mi = 0; mi < 4; ++mi) {
            int m = bm * 128 + wm * 64 + mi * 16 + g;
#pragma unroll
            for (int ni = 0; ni < 4; ++ni) {
                int nLoc = bn * 128 + wn * 32 + ni * 8 + 2 * t;
                float b0 = BIAS ? bias[nLoc] : 0.f;
                float b1 = BIAS ? bias[nLoc + 1] : 0.f;
                long base = (long)b * cBatch;
                C[base + (long)(coff + nLoc) * ldc + m]         = acc[mi][ni][0] + b0;
                C[base + (long)(coff + nLoc + 1) * ldc + m]     = acc[mi][ni][1] + b1;
                C[base + (long)(coff + nLoc) * ldc + m + 8]     = acc[mi][ni][2] + b0;
                C[base + (long)(coff + nLoc + 1) * ldc + m + 8] = acc[mi][ni][3] + b1;
            }
        }
    } else {
#pragma unroll
        for (int mi = 0; mi < 4; ++mi) {
            int m = bm * 128 + wm * 64 + mi * 16 + g;
            long r0 = (long)b * cBatch + (long)m * ldc;
            long r1 = r0 + 8L * ldc;
#pragma unroll
            for (int ni = 0; ni < 4; ++ni) {
                int n = bn * 128 + wn * 32 + ni * 8 + 2 * t;
                *(float2*)&C[r0 + n] = make_float2(acc[mi][ni][0], acc[mi][ni][1]);
                *(float2*)&C[r1 + n] = make_float2(acc[mi][ni][2], acc[mi][ni][3]);
            }
        }
    }
}

// ---------------------------------------------------------------------------
// Hi-fi windowed attention. CTA (128 thr) per (b, window). warp = head.
// Output staged in smem, written TOKEN-MAJOR (hout: B x 4096 x 256), coalesced.
// ---------------------------------------------------------------------------
__global__ __launch_bounds__(128)
void hifi_attn(const float* __restrict__ hqkv, float* __restrict__ hout) {
    __shared__ float sq[4][772];
    __shared__ float sto[4][260];
    int g = blockIdx.x, b = blockIdx.y;
    int gh = g >> 5, gw = g & 31;
    int tid = threadIdx.x;
    int t00 = (gh << 7) + (gw << 1);
    const float* base = hqkv + (long)b * 4096 * 768;
#pragma unroll
    for (int it = 0; it < 6; ++it) {
        int idx = tid + it * 128;
        int n = idx / 192, c4 = idx % 192;
        int t = t00 + ((n >> 1) << 6) + (n & 1);
        *(float4*)&sq[n][c4 * 4] = *(const float4*)(base + (long)t * 768 + c4 * 4);
    }
    __syncthreads();

    int head = tid >> 5, lane = tid & 31;
    int n = (lane >> 2) & 3, m = lane & 3;
    const float* qn = &sq[n][head * 64];
    const float* km = &sq[m][256 + head * 64];
    float s = 0.f;
#pragma unroll
    for (int k = 0; k < 64; ++k) s += qn[k] * km[k];
    s *= 0.125f;

    float mx = fmaxf(s, __shfl_xor_sync(0xffffffffu, s, 1));
    mx = fmaxf(mx, __shfl_xor_sync(0xffffffffu, mx, 2));
    float p = __expf(s - mx);
    float sum = p;
    sum += __shfl_xor_sync(0xffffffffu, sum, 1);
    sum += __shfl_xor_sync(0xffffffffu, sum, 2);
    p = p / sum;

    int no = lane >> 3;
    int d0 = (lane & 7) << 3;
    float o[8];
#pragma unroll
    for (int dd = 0; dd < 8; ++dd) o[dd] = 0.f;
#pragma unroll
    for (int mm = 0; mm < 4; ++mm) {
        float pm = __shfl_sync(0xffffffffu, p, no * 4 + mm);
        const float* vm = &sq[mm][512 + head * 64 + d0];
#pragma unroll
        for (int dd = 0; dd < 8; ++dd) o[dd] += pm * vm[dd];
    }
    int c0 = head * 64 + d0;
    *(float4*)&sto[no][c0]     = make_float4(o[0], o[1], o[2], o[3]);
    *(float4*)&sto[no][c0 + 4] = make_float4(o[4], o[5], o[6], o[7]);
    __syncthreads();

#pragma unroll
    for (int it = 0; it < 2; ++it) {
        int idx = tid + it * 128;               // 256 float4 total
        int tok = idx >> 6, c4 = (idx & 63) << 2;
        int t = t00 + ((tok >> 1) << 6) + (tok & 1);
        *(float4*)(hout + ((long)b * 4096 + t) * 256 + c4) = *(float4*)&sto[tok][c4];
    }
}

// ---------------------------------------------------------------------------
// Lo-fi flash attention, TF32 mma. CTA = 128 queries x (b, head). 8 warps,
// warp = 16-row band. cp.async 3-stage KV ring (raw f32, cvt at consume).
// K stride 68, V stride 72 -> both fragment patterns conflict-free.
// Output staged in smem, written TOKEN-MAJOR (lo: B x 4096 x 256).
// ---------------------------------------------------------------------------
#define FKS 68
#define FVS 72
#define F_STG (64 * FKS + 64 * FVS)   // 8960 words
#define F_SMEM (3 * F_STG * 4)

__global__ __launch_bounds__(256, 1)
void lofi_flash(const float* __restrict__ lq, const float* __restrict__ lkv,
                float* __restrict__ lo) {
    extern __shared__ float fs[];
    int tid = threadIdx.x;
    int warp = tid >> 5, lane = tid & 31;
    int g = lane >> 2, t = lane & 3;
    int qb = blockIdx.x, head = blockIdx.y, b = blockIdx.z;
    int t0 = qb << 7;

    // stage Q (128x64, scaled, f32) into stage-0 region; frags to regs
    const float* lqb = lq + ((long)(b * 4096 + t0)) * 256 + head * 64;
#pragma unroll
    for (int it = 0; it < 8; ++it) {
        int idx = tid + it * 256;
        int r = idx >> 4, d4 = (idx & 15) << 2;
        float4 v = *(const float4*)(lqb + r * 256 + d4);
        v.x *= 0.125f; v.y *= 0.125f; v.z *= 0.125f; v.w *= 0.125f;
        *(float4*)&fs[r * FKS + d4] = v;
    }
    __syncthreads();

    int r0 = warp * 16 + g;
    unsigned qa[8][4];
#pragma unroll
    for (int kk = 0; kk < 8; ++kk) {
        qa[kk][0] = f2tf(fs[r0 * FKS + kk * 8 + t]);
        qa[kk][1] = f2tf(fs[(r0 + 8) * FKS + kk * 8 + t]);
        qa[kk][2] = f2tf(fs[r0 * FKS + kk * 8 + t + 4]);
        qa[kk][3] = f2tf(fs[(r0 + 8) * FKS + kk * 8 + t + 4]);
    }
    __syncthreads();

    float oa[8][4];
#pragma unroll
    for (int nj = 0; nj < 8; ++nj)
#pragma unroll
        for (int r = 0; r < 4; ++r) oa[nj][r] = 0.f;
    float m0 = -1e30f, m1 = -1e30f, l0 = 0.f, l1 = 0.f;

    const float* kvb = lkv + (long)b * 524288 + head * 64;

    auto issue = [&](int st) {
        float* bK = fs + (st % 3) * F_STG;
        float* bV = bK + 64 * FKS;
#pragma unroll
        for (int it = 0; it < 4; ++it) {
            int idx = tid + it * 256;
            int key = idx >> 4, d4 = (idx & 15) << 2;
            const float* row = kvb + (long)(st * 64 + key) * 512;
            cpasync16(&bK[key * FKS + d4], row + d4);
            cpasync16(&bV[key * FVS + d4], row + 256 + d4);
        }
    };
    issue(0); CP_COMMIT;
    issue(1); CP_COMMIT;

    for (int ch = 0; ch < 16; ++ch) {
        CP_WAIT1;
        __syncthreads();
        if (ch + 2 < 16) issue(ch + 2);
        CP_COMMIT;
        const float* sK = fs + (ch % 3) * F_STG;
        const float* sV = sK + 64 * FKS;

        // S = Q K^T
        float s[8][4];
#pragma unroll
        for (int nj = 0; nj < 8; ++nj)
#pragma unroll
            for (int r = 0; r < 4; ++r) s[nj][r] = 0.f;
#pragma unroll
        for (int kk = 0; kk < 8; ++kk) {
            int kO = kk * 8;
#pragma unroll
            for (int nj = 0; nj < 8; ++nj) {
                unsigned b0 = f2tf(sK[(nj * 8 + g) * FKS + kO + t]);
                unsigned b1 = f2tf(sK[(nj * 8 + g) * FKS + kO + t + 4]);
                mma8(s[nj], qa[kk], b0, b1);
            }
        }

        // online softmax (rows r0 -> regs 0,1 ; r0+8 -> regs 2,3)
        float mx0 = -1e30f, mx1 = -1e30f;
#pragma unroll
        for (int nj = 0; nj < 8; ++nj) {
            mx0 = fmaxf(mx0, fmaxf(s[nj][0], s[nj][1]));
            mx1 = fmaxf(mx1, fmaxf(s[nj][2], s[nj][3]));
        }
        mx0 = fmaxf(mx0, __shfl_xor_sync(0xffffffffu, mx0, 1));
        mx0 = fmaxf(mx0, __shfl_xor_sync(0xffffffffu, mx0, 2));
        mx1 = fmaxf(mx1, __shfl_xor_sync(0xffffffffu, mx1, 1));
        mx1 = fmaxf(mx1, __shfl_xor_sync(0xffffffffu, mx1, 2));
        float mn0 = fmaxf(m0, mx0), mn1 = fmaxf(m1, mx1);
        float al0 = __expf(m0 - mn0), al1 = __expf(m1 - mn1);
        float sum0 = 0.f, sum1 = 0.f;
#pragma unroll
        for (int nj = 0; nj < 8; ++nj) {
            s[nj][0] = __expf(s[nj][0] - mn0); sum0 += s[nj][0];
            s[nj][1] = __expf(s[nj][1] - mn0); sum0 += s[nj][1];
            s[nj][2] = __expf(s[nj][2] - mn1); sum1 += s[nj][2];
            s[nj][3] = __expf(s[nj][3] - mn1); sum1 += s[nj][3];
        }
        sum0 += __shfl_xor_sync(0xffffffffu, sum0, 1);
        sum0 += __shfl_xor_sync(0xffffffffu, sum0, 2);
        sum1 += __shfl_xor_sync(0xffffffffu, sum1, 1);
        sum1 += __shfl_xor_sync(0xffffffffu, sum1, 2);
        l0 = l0 * al0 + sum0; m0 = mn0;
        l1 = l1 * al1 + sum1; m1 = mn1;
#pragma unroll
        for (int nj = 0; nj < 8; ++nj) {
            oa[nj][0] *= al0; oa[nj][1] *= al0;
            oa[nj][2] *= al1; oa[nj][3] *= al1;
        }

        // O += P V : P fragments via intra-quad shuffles
        int srcA = (lane & ~3) | (t >> 1);
        int p1 = t & 1;
#pragma unroll
        for (int kk = 0; kk < 8; ++kk) {
            float x0 = __shfl_sync(0xffffffffu, s[kk][0], srcA);
            float x1 = __shfl_sync(0xffffffffu, s[kk][1], srcA);
            float y0 = __shfl_sync(0xffffffffu, s[kk][0], srcA + 2);
            float y1 = __shfl_sync(0xffffffffu, s[kk][1], srcA + 2);
            float z0 = __shfl_sync(0xffffffffu, s[kk][2], srcA);
            float z1 = __shfl_sync(0xffffffffu, s[kk][3], srcA);
            float w0 = __shfl_sync(0xffffffffu, s[kk][2], srcA + 2);
            float w1 = __shfl_sync(0xffffffffu, s[kk][3], srcA + 2);
            unsigned pa[4];
            pa[0] = f2tf(p1 ? x1 : x0);
            pa[2] = f2tf(p1 ? y1 : y0);
            pa[1] = f2tf(p1 ? z1 : z0);
            pa[3] = f2tf(p1 ? w1 : w0);
            int kO = kk * 8;
#pragma unroll
            for (int nj = 0; nj < 8; ++nj) {
                unsigned b0 = f2tf(sV[(kO + t) * FVS + nj * 8 + g]);
                unsigned b1 = f2tf(sV[(kO + t + 4) * FVS + nj * 8 + g]);
                mma8(oa[nj], pa, b0, b1);
            }
        }
    }

    // epilogue: stage 128x64 head-slice in smem, write token-major coalesced
    __syncthreads();
    float inv0 = __frcp_rn(l0), inv1 = __frcp_rn(l1);
#pragma unroll
    for (int nj = 0; nj < 8; ++nj) {
        int c = nj * 8 + 2 * t;
        fs[r0 * FKS + c]           = oa[nj][0] * inv0;
        fs[r0 * FKS + c + 1]       = oa[nj][1] * inv0;
        fs[(r0 + 8) * FKS + c]     = oa[nj][2] * inv1;
        fs[(r0 + 8) * FKS + c + 1] = oa[nj][3] * inv1;
    }
    __syncthreads();
#pragma unroll
    for (int it = 0; it < 8; ++it) {
        int idx = tid + it * 256;             // 2048 float4
        int r = idx >> 4, c4 = (idx & 15) << 2;
        *(float4*)(lo + ((long)(b * 4096 + t0 + r)) * 256 + head * 64 + c4) =
            *(float4*)&fs[r * FKS + c4];
    }
}

// ---------------------------------------------------------------------------
extern "C" void kernel_launch(void* const* d_in, const int* in_sizes, int n_in,
                              void* d_out, int out_size) {
    const float* x        = (const float*)d_in[0];
    const float* h_qkv_w  = (const float*)d_in[1];
    const float* h_proj_w = (const float*)d_in[2];
    const float* h_proj_b = (const float*)d_in[3];
    const float* l_q_w    = (const float*)d_in[4];
    const float* l_kv_w   = (const float*)d_in[5];
    const float* l_proj_w = (const float*)d_in[6];
    const float* l_proj_b = (const float*)d_in[7];
    float* out = (float*)d_out;

    float* scratch = nullptr;
    cudaGetSymbolAddress((void**)&scratch, g_scratch);
    float* pooledT = scratch + OFF_POOL;
    float* hqkv    = scratch + OFF_HQKV;
    float* lqv     = scratch + OFF_LQ;
    float* lkv     = scratch + OFF_LKV;
    float* hout    = scratch + OFF_HOUT;
    float* lov     = scratch + OFF_LOT;

    cudaFuncSetAttribute(tgemm_tn<0, 0>,
                         cudaFuncAttributeMaxDynamicSharedMemorySize, TN_SMEM);
    cudaFuncSetAttribute(tgemm_nt<1, 1>,
                         cudaFuncAttributeMaxDynamicSharedMemorySize, NT_SMEM);
    cudaFuncSetAttribute(lofi_flash,
                         cudaFuncAttributeMaxDynamicSharedMemorySize, F_SMEM);

    pool_kernel<<<8192, 256>>>(x, pooledT);

    // hqkv (B,4096,768) = x^T @ h_qkv_w
    tgemm_tn<0, 0><<<dim3(32, 6, NBATCH), 256, TN_SMEM>>>(
        x, 2097152L, 4096, h_qkv_w, 768, hqkv, 4096L * 768, 768, 0, nullptr, 512);
    // lq (B,4096,256) = x^T @ l_q_w
    tgemm_tn<0, 0><<<dim3(32, 2, NBATCH), 256, TN_SMEM>>>(
        x, 2097152L, 4096, l_q_w, 256, lqv, 4096L * 256, 256, 0, nullptr, 512);
    // lkv (B,1024,512) = pooled^T @ l_kv_w
    tgemm_tn<0, 0><<<dim3(8, 4, NBATCH), 256, TN_SMEM>>>(
        pooledT, 524288L, 1024, l_kv_w, 512, lkv, 1024L * 512, 512, 0, nullptr, 512);

    hifi_attn<<<dim3(1024, NBATCH), 128>>>(hqkv, hout);
    lofi_flash<<<dim3(32, 4, NBATCH), 256, F_SMEM>>>(lqv, lkv, lov);

    // out[:, 0:256]  = hout @ h_proj_w + b   (NCHW channel-major epilogue)
    tgemm_nt<1, 1><<<dim3(32, 2, NBATCH), 256, NT_SMEM>>>(
        hout, 1048576L, 256, h_proj_w, 256, out, 2097152L, 4096, 0, h_proj_b, 256);
    // out[:, 256:512] = lo @ l_proj_w + b
    tgemm_nt<1, 1><<<dim3(32, 2, NBATCH), 256, NT_SMEM>>>(
        lov, 1048576L, 256, l_proj_w, 256, out, 2097152L, 4096, 256, l_proj_b, 256);
}

// round 13
// speedup vs baseline: 2.5923x; 1.0044x over previous
#include <cuda_runtime.h>

// ---------------------------------------------------------------------------
// HiLo attention. TF32 tensor cores (mma.m16n8k8), fp32 accumulate.
// cp.async 3-stage pipelines; token-major intermediates; coalesced epilogues.
// This round: __launch_bounds__(256, 2) on GEMMs + flash (reg-capped so two
// CTAs co-reside per SM; smem already fits 2x within 228 KB).
// ---------------------------------------------------------------------------

#define NBATCH 4

// scratch layout (floats)
#define OFF_POOL  0L                  // pooledT (B,512,1024)
#define OFF_HQKV  2097152L            // hqkv    (B,4096,768)   token-major
#define OFF_LQ    14680064L           // lq      (B,4096,256)   token-major
#define OFF_LKV   18874368L           // lkv     (B,1024,512)   token-major
#define OFF_HOUT  20971520L           // hout    (B,4096,256)   token-major
#define OFF_LOT   25165824L           // lo      (B,4096,256)   token-major
#define SCRATCH_FLOATS 29360128L

__device__ float g_scratch[SCRATCH_FLOATS];

// ---------------------------------------------------------------------------
__device__ __forceinline__ unsigned f2tf(float f) {
    unsigned r;
    asm("cvt.rna.tf32.f32 %0, %1;" : "=r"(r) : "f"(f));
    return r;
}

__device__ __forceinline__ void mma8(float* d, const unsigned* a,
                                     unsigned b0, unsigned b1) {
    asm volatile(
        "mma.sync.aligned.m16n8k8.row.col.f32.tf32.tf32.f32 "
        "{%0,%1,%2,%3}, {%4,%5,%6,%7}, {%8,%9}, {%0,%1,%2,%3};\n"
        : "+f"(d[0]), "+f"(d[1]), "+f"(d[2]), "+f"(d[3])
        : "r"(a[0]), "r"(a[1]), "r"(a[2]), "r"(a[3]), "r"(b0), "r"(b1));
}

__device__ __forceinline__ void cpasync16(void* smem, const void* gmem) {
    unsigned s = (unsigned)__cvta_generic_to_shared(smem);
    asm volatile("cp.async.cg.shared.global [%0], [%1], 16;" :: "r"(s), "l"(gmem));
}
#define CP_COMMIT asm volatile("cp.async.commit_group;")
#define CP_WAIT1  asm volatile("cp.async.wait_group 1;")

// ---------------------------------------------------------------------------
// 2x2 mean pool:  pooledT[b][c][g]
// ---------------------------------------------------------------------------
__global__ __launch_bounds__(256)
void pool_kernel(const float* __restrict__ x, float* __restrict__ pooledT) {
    long idx = (long)blockIdx.x * 256 + threadIdx.x;
    int g = (int)(idx & 1023);
    int c = (int)((idx >> 10) & 511);
    int b = (int)(idx >> 19);
    int gh = g >> 5, gw = g & 31;
    const float* p = x + ((long)(b * 512 + c) << 12) + (gh << 7) + (gw << 1);
    pooledT[idx] = 0.25f * (p[0] + p[1] + p[64] + p[65]);
}

// ---------------------------------------------------------------------------
// TF32 TN GEMM (A stored K-major: K x lda). 128x128 tile, BK=32, 3-stage
// cp.async ring, raw f32 in smem, cvt at fragment load. SGS=136 (conflict-free).
// ---------------------------------------------------------------------------
#define SGS 136
#define TN_STG 8704   // words per stage (As 32*136 + Bs 32*136)
#define TN_SMEM (3 * TN_STG * 4)

template<int TRANSC, int BIAS>
__global__ __launch_bounds__(256, 2)
void tgemm_tn(const float* __restrict__ A, long aBatch, int lda,
              const float* __restrict__ Bw, int ldb,
              float* __restrict__ C, long cBatch, int ldc, int coff,
              const float* __restrict__ bias, int K) {
    extern __shared__ float ts[];
    int tid = threadIdx.x;
    int bm = blockIdx.x, bn = blockIdx.y, b = blockIdx.z;
    const float* Ab = A + (long)b * aBatch + bm * 128;
    const float* Bb = Bw + bn * 128;
    int lk = tid >> 5, lm4 = (tid & 31) << 2;
    int warp = tid >> 5, lane = tid & 31;
    int wm = warp >> 2, wn = warp & 3;
    int g = lane >> 2, t = lane & 3;

    float acc[4][4][4];
#pragma unroll
    for (int i = 0; i < 4; i++)
#pragma unroll
        for (int j = 0; j < 4; j++)
#pragma unroll
            for (int r = 0; r < 4; r++) acc[i][j][r] = 0.f;

    int KT = K >> 5;
    auto issue = [&](int st) {
        float* As = ts + (st % 3) * TN_STG;
        float* Bs = As + 32 * SGS;
#pragma unroll
        for (int it = 0; it < 4; ++it) {
            int k = lk + 8 * it;
            cpasync16(&As[k * SGS + lm4], Ab + (long)(st * 32 + k) * lda + lm4);
            cpasync16(&Bs[k * SGS + lm4], Bb + (long)(st * 32 + k) * ldb + lm4);
        }
    };
    issue(0); CP_COMMIT;
    issue(1); CP_COMMIT;

    for (int kt = 0; kt < KT; ++kt) {
        CP_WAIT1;
        __syncthreads();
        if (kt + 2 < KT) issue(kt + 2);
        CP_COMMIT;
        const float* As = ts + (kt % 3) * TN_STG;
        const float* Bs = As + 32 * SGS;
#pragma unroll
        for (int kk = 0; kk < 4; ++kk) {
            int kO = kk * 8;
            unsigned af[4][4], bf[4][2];
#pragma unroll
            for (int mi = 0; mi < 4; ++mi) {
                int m = wm * 64 + mi * 16 + g;
                af[mi][0] = f2tf(As[(kO + t) * SGS + m]);
                af[mi][1] = f2tf(As[(kO + t) * SGS + m + 8]);
                af[mi][2] = f2tf(As[(kO + t + 4) * SGS + m]);
                af[mi][3] = f2tf(As[(kO + t + 4) * SGS + m + 8]);
            }
#pragma unroll
            for (int ni = 0; ni < 4; ++ni) {
                int n = wn * 32 + ni * 8 + g;
                bf[ni][0] = f2tf(Bs[(kO + t) * SGS + n]);
                bf[ni][1] = f2tf(Bs[(kO + t + 4) * SGS + n]);
            }
#pragma unroll
            for (int mi = 0; mi < 4; ++mi)
#pragma unroll
                for (int ni = 0; ni < 4; ++ni)
                    mma8(acc[mi][ni], af[mi], bf[ni][0], bf[ni][1]);
        }
    }

    if (TRANSC) {
#pragma unroll
        for (int mi = 0; mi < 4; ++mi) {
            int m = bm * 128 + wm * 64 + mi * 16 + g;
#pragma unroll
            for (int ni = 0; ni < 4; ++ni) {
                int nLoc = bn * 128 + wn * 32 + ni * 8 + 2 * t;
                float b0 = BIAS ? bias[nLoc] : 0.f;
                float b1 = BIAS ? bias[nLoc + 1] : 0.f;
                long base = (long)b * cBatch;
                C[base + (long)(coff + nLoc) * ldc + m]         = acc[mi][ni][0] + b0;
                C[base + (long)(coff + nLoc + 1) * ldc + m]     = acc[mi][ni][1] + b1;
                C[base + (long)(coff + nLoc) * ldc + m + 8]     = acc[mi][ni][2] + b0;
                C[base + (long)(coff + nLoc + 1) * ldc + m + 8] = acc[mi][ni][3] + b1;
            }
        }
    } else {
#pragma unroll
        for (int mi = 0; mi < 4; ++mi) {
            int m = bm * 128 + wm * 64 + mi * 16 + g;
            long r0 = (long)b * cBatch + (long)m * ldc;
            long r1 = r0 + 8L * ldc;
#pragma unroll
            for (int ni = 0; ni < 4; ++ni) {
                int n = bn * 128 + wn * 32 + ni * 8 + 2 * t;
                *(float2*)&C[r0 + n] = make_float2(acc[mi][ni][0], acc[mi][ni][1]);
                *(float2*)&C[r1 + n] = make_float2(acc[mi][ni][2], acc[mi][ni][3]);
            }
        }
    }
}

// ---------------------------------------------------------------------------
// TF32 NT GEMM (A row-major: M x lda, lda = K). As stored [m][36] (conflict-
// free: bank = (4m+k)&31). Same pipeline/epilogue as TN.
// ---------------------------------------------------------------------------
#define NTA 36
#define NT_STG (128 * NTA + 32 * SGS)   // 4608 + 4352 = 8960 words
#define NT_SMEM (3 * NT_STG * 4)

template<int TRANSC, int BIAS>
__global__ __launch_bounds__(256, 2)
void tgemm_nt(const float* __restrict__ A, long aBatch, int lda,
              const float* __restrict__ Bw, int ldb,
              float* __restrict__ C, long cBatch, int ldc, int coff,
              const float* __restrict__ bias, int K) {
    extern __shared__ float ns[];
    int tid = threadIdx.x;
    int bm = blockIdx.x, bn = blockIdx.y, b = blockIdx.z;
    const float* Ab = A + (long)b * aBatch + (long)(bm * 128) * lda;
    const float* Bb = Bw + bn * 128;
    int am = tid & 127, ah = tid >> 7;
    int lk = tid >> 5, lm4 = (tid & 31) << 2;
    int warp = tid >> 5, lane = tid & 31;
    int wm = warp >> 2, wn = warp & 3;
    int g = lane >> 2, t = lane & 3;

    float acc[4][4][4];
#pragma unroll
    for (int i = 0; i < 4; i++)
#pragma unroll
        for (int j = 0; j < 4; j++)
#pragma unroll
            for (int r = 0; r < 4; r++) acc[i][j][r] = 0.f;

    int KT = K >> 5;
    auto issue = [&](int st) {
        float* As = ns + (st % 3) * NT_STG;
        float* Bs = As + 128 * NTA;
        const float* Asrc = Ab + (long)am * lda + st * 32 + ah * 16;
#pragma unroll
        for (int j = 0; j < 4; ++j)
            cpasync16(&As[am * NTA + ah * 16 + j * 4], Asrc + j * 4);
#pragma unroll
        for (int it = 0; it < 4; ++it) {
            int k = lk + 8 * it;
            cpasync16(&Bs[k * SGS + lm4], Bb + (long)(st * 32 + k) * ldb + lm4);
        }
    };
    issue(0); CP_COMMIT;
    issue(1); CP_COMMIT;

    for (int kt = 0; kt < KT; ++kt) {
        CP_WAIT1;
        __syncthreads();
        if (kt + 2 < KT) issue(kt + 2);
        CP_COMMIT;
        const float* As = ns + (kt % 3) * NT_STG;
        const float* Bs = As + 128 * NTA;
#pragma unroll
        for (int kk = 0; kk < 4; ++kk) {
            int kO = kk * 8;
            unsigned af[4][4], bf[4][2];
#pragma unroll
            for (int mi = 0; mi < 4; ++mi) {
                int m = wm * 64 + mi * 16 + g;
                af[mi][0] = f2tf(As[m * NTA + kO + t]);
                af[mi][1] = f2tf(As[(m + 8) * NTA + kO + t]);
                af[mi][2] = f2tf(As[m * NTA + kO + t + 4]);
                af[mi][3] = f2tf(As[(m + 8) * NTA + kO + t + 4]);
            }
#pragma unroll
            for (int ni = 0; ni < 4; ++ni) {
                int n = wn * 32 + ni * 8 + g;
                bf[ni][0] = f2tf(Bs[(kO + t) * SGS + n]);
                bf[ni][1] = f2tf(Bs[(kO + t + 4) * SGS + n]);
            }
#pragma unroll
            for (int mi = 0; mi < 4; ++mi)
#pragma unroll
                for (int ni = 0; ni < 4; ++ni)
                    mma8(acc[mi][ni], af[mi], bf[ni][0], bf[ni][1]);
        }
    }

    if (TRANSC) {
#pragma unroll
        for (int mi = 0; mi < 4; ++mi) {
            int m = bm * 128 + wm * 64 + mi * 16 + g;
#pragma unroll
            for (int ni = 0; ni < 4; ++ni) {
                int nLoc = bn * 128 + wn * 32 + ni * 8 + 2 * t;
                float b0 = BIAS ? bias[nLoc] : 0.f;
                float b1 = BIAS ? bias[nLoc + 1] : 0.f;
                long base = (long)b * cBatch;
                C[base + (long)(coff + nLoc) * ldc + m]         = acc[mi][ni][0] + b0;
                C[base + (long)(coff + nLoc + 1) * ldc + m]     = acc[mi][ni][1] + b1;
                C[base + (long)(coff + nLoc) * ldc + m + 8]     = acc[mi][ni][2] + b0;
                C[base + (long)(coff + nLoc + 1) * ldc + m + 8] = acc[mi][ni][3] + b1;
            }
        }
    } else {
#pragma unroll
        for (int mi = 0; mi < 4; ++mi) {
            int m = bm * 128 + wm * 64 + mi * 16 + g;
            long r0 = (long)b * cBatch + (long)m * ldc;
            long r1 = r0 + 8L * ldc;
#pragma unroll
            for (int ni = 0; ni < 4; ++ni) {
                int n = bn * 128 + wn * 32 + ni * 8 + 2 * t;
                *(float2*)&C[r0 + n] = make_float2(acc[mi][ni][0], acc[mi][ni][1]);
                *(float2*)&C[r1 + n] = make_float2(acc[mi][ni][2], acc[mi][ni][3]);
            }
        }
    }
}

// ---------------------------------------------------------------------------
// Hi-fi windowed attention. CTA (128 thr) per (b, window). warp = head.
// Output staged in smem, written TOKEN-MAJOR (hout: B x 4096 x 256), coalesced.
// ---------------------------------------------------------------------------
__global__ __launch_bounds__(128)
void hifi_attn(const float* __restrict__ hqkv, float* __restrict__ hout) {
    __shared__ float sq[4][772];
    __shared__ float sto[4][260];
    int g = blockIdx.x, b = blockIdx.y;
    int gh = g >> 5, gw = g & 31;
    int tid = threadIdx.x;
    int t00 = (gh << 7) + (gw << 1);
    const float* base = hqkv + (long)b * 4096 * 768;
#pragma unroll
    for (int it = 0; it < 6; ++it) {
        int idx = tid + it * 128;
        int n = idx / 192, c4 = idx % 192;
        int t = t00 + ((n >> 1) << 6) + (n & 1);
        *(float4*)&sq[n][c4 * 4] = *(const float4*)(base + (long)t * 768 + c4 * 4);
    }
    __syncthreads();

    int head = tid >> 5, lane = tid & 31;
    int n = (lane >> 2) & 3, m = lane & 3;
    const float* qn = &sq[n][head * 64];
    const float* km = &sq[m][256 + head * 64];
    float s = 0.f;
#pragma unroll
    for (int k = 0; k < 64; ++k) s += qn[k] * km[k];
    s *= 0.125f;

    float mx = fmaxf(s, __shfl_xor_sync(0xffffffffu, s, 1));
    mx = fmaxf(mx, __shfl_xor_sync(0xffffffffu, mx, 2));
    float p = __expf(s - mx);
    float sum = p;
    sum += __shfl_xor_sync(0xffffffffu, sum, 1);
    sum += __shfl_xor_sync(0xffffffffu, sum, 2);
    p = p / sum;

    int no = lane >> 3;
    int d0 = (lane & 7) << 3;
    float o[8];
#pragma unroll
    for (int dd = 0; dd < 8; ++dd) o[dd] = 0.f;
#pragma unroll
    for (int mm = 0; mm < 4; ++mm) {
        float pm = __shfl_sync(0xffffffffu, p, no * 4 + mm);
        const float* vm = &sq[mm][512 + head * 64 + d0];
#pragma unroll
        for (int dd = 0; dd < 8; ++dd) o[dd] += pm * vm[dd];
    }
    int c0 = head * 64 + d0;
    *(float4*)&sto[no][c0]     = make_float4(o[0], o[1], o[2], o[3]);
    *(float4*)&sto[no][c0 + 4] = make_float4(o[4], o[5], o[6], o[7]);
    __syncthreads();

#pragma unroll
    for (int it = 0; it < 2; ++it) {
        int idx = tid + it * 128;               // 256 float4 total
        int tok = idx >> 6, c4 = (idx & 63) << 2;
        int t = t00 + ((tok >> 1) << 6) + (tok & 1);
        *(float4*)(hout + ((long)b * 4096 + t) * 256 + c4) = *(float4*)&sto[tok][c4];
    }
}

// ---------------------------------------------------------------------------
// Lo-fi flash attention, TF32 mma. CTA = 128 queries x (b, head). 8 warps,
// warp = 16-row band. cp.async 3-stage KV ring (raw f32, cvt at consume).
// K stride 68, V stride 72 -> both fragment patterns conflict-free.
// Output staged in smem, written TOKEN-MAJOR (lo: B x 4096 x 256).
// ---------------------------------------------------------------------------
#define FKS 68
#define FVS 72
#define F_STG (64 * FKS + 64 * FVS)   // 8960 words
#define F_SMEM (3 * F_STG * 4)

__global__ __launch_bounds__(256, 2)
void lofi_flash(const float* __restrict__ lq, const float* __restrict__ lkv,
                float* __restrict__ lo) {
    extern __shared__ float fs[];
    int tid = threadIdx.x;
    int warp = tid >> 5, lane = tid & 31;
    int g = lane >> 2, t = lane & 3;
    int qb = blockIdx.x, head = blockIdx.y, b = blockIdx.z;
    int t0 = qb << 7;

    // stage Q (128x64, scaled, f32) into stage-0 region; frags to regs
    const float* lqb = lq + ((long)(b * 4096 + t0)) * 256 + head * 64;
#pragma unroll
    for (int it = 0; it < 8; ++it) {
        int idx = tid + it * 256;
        int r = idx >> 4, d4 = (idx & 15) << 2;
        float4 v = *(const float4*)(lqb + r * 256 + d4);
        v.x *= 0.125f; v.y *= 0.125f; v.z *= 0.125f; v.w *= 0.125f;
        *(float4*)&fs[r * FKS + d4] = v;
    }
    __syncthreads();

    int r0 = warp * 16 + g;
    unsigned qa[8][4];
#pragma unroll
    for (int kk = 0; kk < 8; ++kk) {
        qa[kk][0] = f2tf(fs[r0 * FKS + kk * 8 + t]);
        qa[kk][1] = f2tf(fs[(r0 + 8) * FKS + kk * 8 + t]);
        qa[kk][2] = f2tf(fs[r0 * FKS + kk * 8 + t + 4]);
        qa[kk][3] = f2tf(fs[(r0 + 8) * FKS + kk * 8 + t + 4]);
    }
    __syncthreads();

    float oa[8][4];
#pragma unroll
    for (int nj = 0; nj < 8; ++nj)
#pragma unroll
        for (int r = 0; r < 4; ++r) oa[nj][r] = 0.f;
    float m0 = -1e30f, m1 = -1e30f, l0 = 0.f, l1 = 0.f;

    const float* kvb = lkv + (long)b * 524288 + head * 64;

    auto issue = [&](int st) {
        float* bK = fs + (st % 3) * F_STG;
        float* bV = bK + 64 * FKS;
#pragma unroll
        for (int it = 0; it < 4; ++it) {
            int idx = tid + it * 256;
            int key = idx >> 4, d4 = (idx & 15) << 2;
            const float* row = kvb + (long)(st * 64 + key) * 512;
            cpasync16(&bK[key * FKS + d4], row + d4);
            cpasync16(&bV[key * FVS + d4], row + 256 + d4);
        }
    };
    issue(0); CP_COMMIT;
    issue(1); CP_COMMIT;

    for (int ch = 0; ch < 16; ++ch) {
        CP_WAIT1;
        __syncthreads();
        if (ch + 2 < 16) issue(ch + 2);
        CP_COMMIT;
        const float* sK = fs + (ch % 3) * F_STG;
        const float* sV = sK + 64 * FKS;

        // S = Q K^T
        float s[8][4];
#pragma unroll
        for (int nj = 0; nj < 8; ++nj)
#pragma unroll
            for (int r = 0; r < 4; ++r) s[nj][r] = 0.f;
#pragma unroll
        for (int kk = 0; kk < 8; ++kk) {
            int kO = kk * 8;
#pragma unroll
            for (int nj = 0; nj < 8; ++nj) {
                unsigned b0 = f2tf(sK[(nj * 8 + g) * FKS + kO + t]);
                unsigned b1 = f2tf(sK[(nj * 8 + g) * FKS + kO + t + 4]);
                mma8(s[nj], qa[kk], b0, b1);
            }
        }

        // online softmax (rows r0 -> regs 0,1 ; r0+8 -> regs 2,3)
        float mx0 = -1e30f, mx1 = -1e30f;
#pragma unroll
        for (int nj = 0; nj < 8; ++nj) {
            mx0 = fmaxf(mx0, fmaxf(s[nj][0], s[nj][1]));
            mx1 = fmaxf(mx1, fmaxf(s[nj][2], s[nj][3]));
        }
        mx0 = fmaxf(mx0, __shfl_xor_sync(0xffffffffu, mx0, 1));
        mx0 = fmaxf(mx0, __shfl_xor_sync(0xffffffffu, mx0, 2));
        mx1 = fmaxf(mx1, __shfl_xor_sync(0xffffffffu, mx1, 1));
        mx1 = fmaxf(mx1, __shfl_xor_sync(0xffffffffu, mx1, 2));
        float mn0 = fmaxf(m0, mx0), mn1 = fmaxf(m1, mx1);
        float al0 = __expf(m0 - mn0), al1 = __expf(m1 - mn1);
        float sum0 = 0.f, sum1 = 0.f;
#pragma unroll
        for (int nj = 0; nj < 8; ++nj) {
            s[nj][0] = __expf(s[nj][0] - mn0); sum0 += s[nj][0];
            s[nj][1] = __expf(s[nj][1] - mn0); sum0 += s[nj][1];
            s[nj][2] = __expf(s[nj][2] - mn1); sum1 += s[nj][2];
            s[nj][3] = __expf(s[nj][3] - mn1); sum1 += s[nj][3];
        }
        sum0 += __shfl_xor_sync(0xffffffffu, sum0, 1);
        sum0 += __shfl_xor_sync(0xffffffffu, sum0, 2);
        sum1 += __shfl_xor_sync(0xffffffffu, sum1, 1);
        sum1 += __shfl_xor_sync(0xffffffffu, sum1, 2);
        l0 = l0 * al0 + sum0; m0 = mn0;
        l1 = l1 * al1 + sum1; m1 = mn1;
#pragma unroll
        for (int nj = 0; nj < 8; ++nj) {
            oa[nj][0] *= al0; oa[nj][1] *= al0;
            oa[nj][2] *= al1; oa[nj][3] *= al1;
        }

        // O += P V : P fragments via intra-quad shuffles
        int srcA = (lane & ~3) | (t >> 1);
        int p1 = t & 1;
#pragma unroll
        for (int kk = 0; kk < 8; ++kk) {
            float x0 = __shfl_sync(0xffffffffu, s[kk][0], srcA);
            float x1 = __shfl_sync(0xffffffffu, s[kk][1], srcA);
            float y0 = __shfl_sync(0xffffffffu, s[kk][0], srcA + 2);
            float y1 = __shfl_sync(0xffffffffu, s[kk][1], srcA + 2);
            float z0 = __shfl_sync(0xffffffffu, s[kk][2], srcA);
            float z1 = __shfl_sync(0xffffffffu, s[kk][3], srcA);
            float w0 = __shfl_sync(0xffffffffu, s[kk][2], srcA + 2);
            float w1 = __shfl_sync(0xffffffffu, s[kk][3], srcA + 2);
            unsigned pa[4];
            pa[0] = f2tf(p1 ? x1 : x0);
            pa[2] = f2tf(p1 ? y1 : y0);
            pa[1] = f2tf(p1 ? z1 : z0);
            pa[3] = f2tf(p1 ? w1 : w0);
            int kO = kk * 8;
#pragma unroll
            for (int nj = 0; nj < 8; ++nj) {
                unsigned b0 = f2tf(sV[(kO + t) * FVS + nj * 8 + g]);
                unsigned b1 = f2tf(sV[(kO + t + 4) * FVS + nj * 8 + g]);
                mma8(oa[nj], pa, b0, b1);
            }
        }
    }

    // epilogue: stage 128x64 head-slice in smem, write token-major coalesced
    __syncthreads();
    float inv0 = __frcp_rn(l0), inv1 = __frcp_rn(l1);
#pragma unroll
    for (int nj = 0; nj < 8; ++nj) {
        int c = nj * 8 + 2 * t;
        fs[r0 * FKS + c]           = oa[nj][0] * inv0;
        fs[r0 * FKS + c + 1]       = oa[nj][1] * inv0;
        fs[(r0 + 8) * FKS + c]     = oa[nj][2] * inv1;
        fs[(r0 + 8) * FKS + c + 1] = oa[nj][3] * inv1;
    }
    __syncthreads();
#pragma unroll
    for (int it = 0; it < 8; ++it) {
        int idx = tid + it * 256;             // 2048 float4
        int r = idx >> 4, c4 = (idx & 15) << 2;
        *(float4*)(lo + ((long)(b * 4096 + t0 + r)) * 256 + head * 64 + c4) =
            *(float4*)&fs[r * FKS + c4];
    }
}

// ---------------------------------------------------------------------------
extern "C" void kernel_launch(void* const* d_in, const int* in_sizes, int n_in,
                              void* d_out, int out_size) {
    const float* x        = (const float*)d_in[0];
    const float* h_qkv_w  = (const float*)d_in[1];
    const float* h_proj_w = (const float*)d_in[2];
    const float* h_proj_b = (const float*)d_in[3];
    const float* l_q_w    = (const float*)d_in[4];
    const float* l_kv_w   = (const float*)d_in[5];
    const float* l_proj_w = (const float*)d_in[6];
    const float* l_proj_b = (const float*)d_in[7];
    float* out = (float*)d_out;

    float* scratch = nullptr;
    cudaGetSymbolAddress((void**)&scratch, g_scratch);
    float* pooledT = scratch + OFF_POOL;
    float* hqkv    = scratch + OFF_HQKV;
    float* lqv     = scratch + OFF_LQ;
    float* lkv     = scratch + OFF_LKV;
    float* hout    = scratch + OFF_HOUT;
    float* lov     = scratch + OFF_LOT;

    cudaFuncSetAttribute(tgemm_tn<0, 0>,
                         cudaFuncAttributeMaxDynamicSharedMemorySize, TN_SMEM);
    cudaFuncSetAttribute(tgemm_nt<1, 1>,
                         cudaFuncAttributeMaxDynamicSharedMemorySize, NT_SMEM);
    cudaFuncSetAttribute(lofi_flash,
                         cudaFuncAttributeMaxDynamicSharedMemorySize, F_SMEM);

    pool_kernel<<<8192, 256>>>(x, pooledT);

    // hqkv (B,4096,768) = x^T @ h_qkv_w
    tgemm_tn<0, 0><<<dim3(32, 6, NBATCH), 256, TN_SMEM>>>(
        x, 2097152L, 4096, h_qkv_w, 768, hqkv, 4096L * 768, 768, 0, nullptr, 512);
    // lq (B,4096,256) = x^T @ l_q_w
    tgemm_tn<0, 0><<<dim3(32, 2, NBATCH), 256, TN_SMEM>>>(
        x, 2097152L, 4096, l_q_w, 256, lqv, 4096L * 256, 256, 0, nullptr, 512);
    // lkv (B,1024,512) = pooled^T @ l_kv_w
    tgemm_tn<0, 0><<<dim3(8, 4, NBATCH), 256, TN_SMEM>>>(
        pooledT, 524288L, 1024, l_kv_w, 512, lkv, 1024L * 512, 512, 0, nullptr, 512);

    hifi_attn<<<dim3(1024, NBATCH), 128>>>(hqkv, hout);
    lofi_flash<<<dim3(32, 4, NBATCH), 256, F_SMEM>>>(lqv, lkv, lov);

    // out[:, 0:256]  = hout @ h_proj_w + b   (NCHW channel-major epilogue)
    tgemm_nt<1, 1><<<dim3(32, 2, NBATCH), 256, NT_SMEM>>>(
        hout, 1048576L, 256, h_proj_w, 256, out, 2097152L, 4096, 0, h_proj_b, 256);
    // out[:, 256:512] = lo @ l_proj_w + b
    tgemm_nt<1, 1><<<dim3(32, 2, NBATCH), 256, NT_SMEM>>>(
        lov, 1048576L, 256, l_proj_w, 256, out, 2097152L, 4096, 256, l_proj_b, 256);
}